// round 1
// baseline (speedup 1.0000x reference)
#include <cuda_runtime.h>
#include <math.h>

// ---------------- scratch (static device globals; no allocation) ----------------
#define NVOX 4194304  // 2*64*32*32*32
static __device__ float g_tmp[NVOX];
static __device__ float g_x1[NVOX];
static __device__ float g_x2[NVOX];
static __device__ float g_acc[NVOX];

// ---------------- helpers ----------------
__device__ __forceinline__ float softplus_f(float x) {
    // stable: max(x,0) + log1p(exp(-|x|))
    return fmaxf(x, 0.f) + log1pf(__expf(-fabsf(x)));
}
__device__ __forceinline__ float silu_f(float x) {
    return x / (1.f + __expf(-x));
}
// exp2 for x <= 0 via degree-5 poly on the FMA pipe (avoids MUFU bottleneck in the scan)
__device__ __forceinline__ float fast_exp2_neg(float x) {
    x = fmaxf(x, -80.f);
    float fn = floorf(x);
    float f = x - fn;                       // [0,1)
    float p = 1.8775767e-3f;
    p = fmaf(p, f, 8.9893397e-3f);
    p = fmaf(p, f, 5.5826318e-2f);
    p = fmaf(p, f, 2.4015361e-1f);
    p = fmaf(p, f, 6.9315308e-1f);
    p = fmaf(p, f, 1.0f);
    int ni = (int)fn;                       // fn <= 0, >= -80
    return p * __int_as_float((ni + 127) << 23);
}

// ---------------- conv3d 3x3x3, C=64->64, +bias ----------------
// grid (16, 32, 2), block 256. Each thread: 8 d-outputs x 2 output channels.
__global__ void conv3d_kernel(const float* __restrict__ xin,
                              const float* __restrict__ cw,
                              const float* __restrict__ cb,
                              float* __restrict__ out) {
    __shared__ float wsh[2 * 1728];
    int tid = threadIdx.x;
    int co0 = blockIdx.y;        // 0..31
    int co1 = co0 + 32;
    int b = blockIdx.z;
    for (int i = tid; i < 1728; i += 256) {
        wsh[i] = cw[co0 * 1728 + i];
        wsh[1728 + i] = cw[co1 * 1728 + i];
    }
    __syncthreads();
    int s = blockIdx.x * 256 + tid;          // 0..4095
    int d0 = (s & 3) * 8;
    int w  = (s >> 2) & 31;
    int h  = s >> 7;
    float acc0[8], acc1[8];
#pragma unroll
    for (int t = 0; t < 8; t++) { acc0[t] = 0.f; acc1[t] = 0.f; }
    for (int ci = 0; ci < 64; ci++) {
        const float* xc = xin + (size_t)(b * 64 + ci) * 32768;
#pragma unroll
        for (int kh = 0; kh < 3; kh++) {
            int hh = h + kh - 1;
            if (hh < 0 || hh >= 32) continue;
#pragma unroll
            for (int kw = 0; kw < 3; kw++) {
                int ww = w + kw - 1;
                if (ww < 0 || ww >= 32) continue;
                const float* row = xc + hh * 1024 + ww * 32;
                float v[10];
#pragma unroll
                for (int dd = 0; dd < 10; dd++) {
                    int d = d0 - 1 + dd;
                    v[dd] = (d >= 0 && d < 32) ? row[d] : 0.f;
                }
                const float* wp = &wsh[ci * 27 + kh * 9 + kw * 3];
                float w00 = wp[0], w01 = wp[1], w02 = wp[2];
                float w10 = wp[1728], w11 = wp[1729], w12 = wp[1730];
#pragma unroll
                for (int t = 0; t < 8; t++) {
                    acc0[t] = fmaf(v[t], w00, fmaf(v[t+1], w01, fmaf(v[t+2], w02, acc0[t])));
                    acc1[t] = fmaf(v[t], w10, fmaf(v[t+1], w11, fmaf(v[t+2], w12, acc1[t])));
                }
            }
        }
    }
    float b0 = cb[co0], b1 = cb[co1];
    float* o0 = out + ((size_t)(b * 64 + co0) * 32 + h) * 1024 + w * 32 + d0;
    float* o1 = out + ((size_t)(b * 64 + co1) * 32 + h) * 1024 + w * 32 + d0;
#pragma unroll
    for (int t = 0; t < 8; t++) { o0[t] = acc0[t] + b0; o1[t] = acc1[t] + b1; }
}

// ---------------- InstanceNorm3d (no affine) + LeakyReLU(0.01) + residual ----------------
// one block per (b,c); 128 blocks x 256 threads
__global__ void inorm_res_kernel(const float* __restrict__ y,
                                 const float* __restrict__ res,
                                 float* __restrict__ out) {
    int bc = blockIdx.x;
    const float4* yp = (const float4*)(y + (size_t)bc * 32768);
    int tid = threadIdx.x;
    float s1 = 0.f, s2 = 0.f;
    for (int i = tid; i < 8192; i += 256) {
        float4 v = yp[i];
        s1 += v.x + v.y + v.z + v.w;
        s2 += v.x * v.x + v.y * v.y + v.z * v.z + v.w * v.w;
    }
    __shared__ float r1[256], r2[256];
    r1[tid] = s1; r2[tid] = s2; __syncthreads();
    for (int o = 128; o > 0; o >>= 1) {
        if (tid < o) { r1[tid] += r1[tid + o]; r2[tid] += r2[tid + o]; }
        __syncthreads();
    }
    float mu = r1[0] * (1.f / 32768.f);
    float var = r2[0] * (1.f / 32768.f) - mu * mu;
    float rstd = rsqrtf(var + 1e-5f);
    const float4* rp = (const float4*)(res + (size_t)bc * 32768);
    float4* op = (float4*)(out + (size_t)bc * 32768);
    for (int i = tid; i < 8192; i += 256) {
        float4 v = yp[i]; float4 r = rp[i]; float4 o; float a;
        a = (v.x - mu) * rstd; o.x = r.x + (a >= 0.f ? a : 0.01f * a);
        a = (v.y - mu) * rstd; o.y = r.y + (a >= 0.f ? a : 0.01f * a);
        a = (v.z - mu) * rstd; o.z = r.z + (a >= 0.f ? a : 0.01f * a);
        a = (v.w - mu) * rstd; o.w = r.w + (a >= 0.f ? a : 0.01f * a);
        op[i] = o;
    }
}

// ---------------- fused per-sequence Mamba ----------------
// grid (2048, 3) blocks, 256 threads. blockIdx.y = axis (0:H, 1:W, 2:D).
#define SMEM_FLOATS 20912
__global__ void mamba_kernel(
    const float* __restrict__ xin,
    const float* __restrict__ ln_w,  const float* __restrict__ ln_b,
    const float* __restrict__ left_w, const float* __restrict__ conv1d_w,
    const float* __restrict__ conv1d_b, const float* __restrict__ delta_w,
    const float* __restrict__ delta_b, const float* __restrict__ Bp_w,
    const float* __restrict__ Cp_w,  const float* __restrict__ A_log,
    const float* __restrict__ right_w, const float* __restrict__ pn_w,
    const float* __restrict__ pn_b,  const float* __restrict__ out_w,
    const float* __restrict__ axis_w,
    float* __restrict__ acc_out)
{
    extern __shared__ float sm[];
    float* XS   = sm;            // [32][65]  x (then layernormed)
    float* XL   = XS + 2080;     // [32][129] left post conv+silu
    float* GA   = XL + 4128;     // [32][129] gate
    float* DS   = GA + 4128;     // [32][129] delta
    float* YS   = DS + 4128;     // [32][129] scan y -> y*gate -> pn
    float* BS   = YS + 4128;     // [32][17]
    float* CS   = BS + 544;      // [32][17]
    float* MUSD = CS + 544;      // [32][2]
    float* A2S  = MUSD + 64;     // [16]
    float* LNW  = A2S + 16;      // [64]
    float* LNB  = LNW + 64;      // [64]
    float* CW   = LNB + 64;      // [512]
    float* CB   = CW + 512;      // [128]
    float* DB   = CB + 128;      // [128]
    float* PNW  = DB + 128;      // [128]
    float* PNB  = PNW + 128;     // [128]
    __shared__ float WA;

    int tid = threadIdx.x;
    int q = blockIdx.x;
    int axis = blockIdx.y;

    int b = q >> 10;
    int u = (q >> 5) & 31;
    int v = q & 31;
    long base; int tstride;
    if (axis == 0)      { base = (long)b * 2097152 + u * 32 + v;   tstride = 1024; }
    else if (axis == 1) { base = (long)b * 2097152 + u * 1024 + v; tstride = 32; }
    else                { base = (long)b * 2097152 + u * 1024 + v * 32; tstride = 1; }

    // phase 0: constants + gather
    for (int i = tid; i < 64; i += 256) { LNW[i] = ln_w[i]; LNB[i] = ln_b[i]; }
    for (int i = tid; i < 128; i += 256) {
        CB[i] = conv1d_b[i]; DB[i] = delta_b[i]; PNW[i] = pn_w[i]; PNB[i] = pn_b[i];
    }
    for (int i = tid; i < 512; i += 256) CW[i] = conv1d_w[i];
    if (tid < 16) A2S[tid] = -softplus_f(A_log[tid]) * 1.44269504f;
    if (tid == 0) {
        float a0 = axis_w[0], a1 = axis_w[1], a2 = axis_w[2];
        float m = fmaxf(a0, fmaxf(a1, a2));
        float e0 = __expf(a0 - m), e1 = __expf(a1 - m), e2 = __expf(a2 - m);
        float inv = 1.f / (e0 + e1 + e2);
        WA = (axis == 0 ? e0 : (axis == 1 ? e1 : e2)) * inv;
    }
    for (int e = tid; e < 2048; e += 256) {
        int t = e >> 6, c = e & 63;
        XS[t * 65 + c] = xin[base + (long)c * 32768 + (long)t * tstride];
    }
    __syncthreads();

    // phase 1: layernorm over C=64 per timestep
    {
        int t = tid >> 3, g = tid & 7;
        float s1 = 0.f, s2 = 0.f;
#pragma unroll
        for (int cc = 0; cc < 8; cc++) {
            float vv = XS[t * 65 + g * 8 + cc];
            s1 += vv; s2 += vv * vv;
        }
#pragma unroll
        for (int o = 4; o > 0; o >>= 1) {
            s1 += __shfl_down_sync(0xffffffffu, s1, o);
            s2 += __shfl_down_sync(0xffffffffu, s2, o);
        }
        if (g == 0) {
            float mu = s1 * (1.f / 64.f);
            float var = s2 * (1.f / 64.f) - mu * mu;
            MUSD[t * 2] = mu;
            MUSD[t * 2 + 1] = rsqrtf(var + 1e-5f);
        }
    }
    __syncthreads();
    for (int e = tid; e < 2048; e += 256) {
        int t = e >> 6, c = e & 63;
        XS[t * 65 + c] = (XS[t * 65 + c] - MUSD[t * 2]) * MUSD[t * 2 + 1] * LNW[c] + LNB[c];
    }
    __syncthreads();

    // phase 2: left/right projections; left -> causal conv1d(k=4) + silu; right -> silu (gate)
    {
        int col = tid & 127;
        int which = tid >> 7;
        const float* Wp = (which ? right_w : left_w) + col * 64;
        float acc[32];
#pragma unroll
        for (int t = 0; t < 32; t++) acc[t] = 0.f;
        for (int k = 0; k < 64; k++) {
            float wv = Wp[k];
#pragma unroll
            for (int t = 0; t < 32; t++) acc[t] = fmaf(XS[t * 65 + k], wv, acc[t]);
        }
        if (which == 0) {
            float c0 = CW[col*4], c1 = CW[col*4+1], c2 = CW[col*4+2], c3 = CW[col*4+3];
            float bb = CB[col];
#pragma unroll
            for (int t = 0; t < 32; t++) {
                float s = fmaf(c3, acc[t], bb);
                if (t >= 1) s = fmaf(c2, acc[t-1], s);
                if (t >= 2) s = fmaf(c1, acc[t-2], s);
                if (t >= 3) s = fmaf(c0, acc[t-3], s);
                XL[t * 129 + col] = silu_f(s);
            }
        } else {
#pragma unroll
            for (int t = 0; t < 32; t++) GA[t * 129 + col] = silu_f(acc[t]);
        }
    }
    __syncthreads();

    // phase 3: delta projection (+softplus+clip) and B/C projections
    {
        int col = tid & 127;
        int tbase = (tid >> 7) * 16;
        const float* Wp = delta_w + col * 128;
        float acc[16];
#pragma unroll
        for (int t = 0; t < 16; t++) acc[t] = 0.f;
        for (int k = 0; k < 128; k++) {
            float wv = Wp[k];
#pragma unroll
            for (int t = 0; t < 16; t++) acc[t] = fmaf(XL[(tbase + t) * 129 + k], wv, acc[t]);
        }
        float bb = DB[col];
#pragma unroll
        for (int t = 0; t < 16; t++) {
            float z = softplus_f(acc[t] + bb);
            DS[(tbase + t) * 129 + col] = fminf(fmaxf(z, 1e-4f), 10.f);
        }
    }
    if (tid < 128) {
        int col = tid & 15;
        int kind = (tid >> 4) & 1;
        int tbase = (tid >> 5) * 8;
        const float* Wp = (kind ? Cp_w : Bp_w) + col * 128;
        float acc[8];
#pragma unroll
        for (int t = 0; t < 8; t++) acc[t] = 0.f;
        for (int k = 0; k < 128; k++) {
            float wv = Wp[k];
#pragma unroll
            for (int t = 0; t < 8; t++) acc[t] = fmaf(XL[(tbase + t) * 129 + k], wv, acc[t]);
        }
        float* dst = kind ? CS : BS;
#pragma unroll
        for (int t = 0; t < 8; t++) dst[(tbase + t) * 17 + col] = acc[t];
    }
    __syncthreads();

    // phase 4: selective scan. thread pair (i, half) owns state h[i, half*8 .. half*8+7]
    {
        int i = tid >> 1;
        int hlf = tid & 1;
        float h[8];
        float a2l[8];
#pragma unroll
        for (int u2 = 0; u2 < 8; u2++) { h[u2] = 0.f; a2l[u2] = A2S[hlf * 8 + u2]; }
        for (int t = 0; t < 32; t++) {
            float d  = DS[t * 129 + i];
            float xv = XL[t * 129 + i];
            float dx = d * xv;
            float part = 0.f;
#pragma unroll
            for (int u2 = 0; u2 < 8; u2++) {
                int sidx = hlf * 8 + u2;
                float e = fast_exp2_neg(d * a2l[u2]);
                h[u2] = fmaf(e, h[u2], dx * BS[t * 17 + sidx]);
                part = fmaf(h[u2], CS[t * 17 + sidx], part);
            }
            part += __shfl_xor_sync(0xffffffffu, part, 1);
            if (hlf == 0) YS[t * 129 + i] = part;
        }
    }
    __syncthreads();

    // phase 5: y *= gate, then layernorm over di=128 per timestep
    for (int e = tid; e < 4096; e += 256) {
        int t = e >> 7, i = e & 127;
        YS[t * 129 + i] *= GA[t * 129 + i];
    }
    __syncthreads();
    {
        int t = tid >> 3, g = tid & 7;
        float s1 = 0.f, s2 = 0.f;
#pragma unroll
        for (int m = 0; m < 16; m++) {
            float vv = YS[t * 129 + g + m * 8];
            s1 += vv; s2 += vv * vv;
        }
#pragma unroll
        for (int o = 4; o > 0; o >>= 1) {
            s1 += __shfl_down_sync(0xffffffffu, s1, o);
            s2 += __shfl_down_sync(0xffffffffu, s2, o);
        }
        if (g == 0) {
            float mu = s1 * (1.f / 128.f);
            float var = s2 * (1.f / 128.f) - mu * mu;
            MUSD[t * 2] = mu;
            MUSD[t * 2 + 1] = rsqrtf(var + 1e-5f);
        }
    }
    __syncthreads();
    for (int e = tid; e < 4096; e += 256) {
        int t = e >> 7, i = e & 127;
        YS[t * 129 + i] = (YS[t * 129 + i] - MUSD[t * 2]) * MUSD[t * 2 + 1] * PNW[i] + PNB[i];
    }
    __syncthreads();

    // phase 6: out projection [32,128]x[128,64] + weighted atomic scatter
    {
        int col = tid & 63;
        int tbase = (tid >> 6) * 8;
        const float* Wp = out_w + col * 128;
        float acc[8];
#pragma unroll
        for (int t = 0; t < 8; t++) acc[t] = 0.f;
        for (int k = 0; k < 128; k++) {
            float wv = Wp[k];
#pragma unroll
            for (int t = 0; t < 8; t++) acc[t] = fmaf(YS[(tbase + t) * 129 + k], wv, acc[t]);
        }
        float wa = WA;
#pragma unroll
        for (int t = 0; t < 8; t++) {
            int tt = tbase + t;
            atomicAdd(&acc_out[base + (long)col * 32768 + (long)tt * tstride], wa * acc[t]);
        }
    }
}

// ---------------- misc ----------------
__global__ void zero_kernel(float* __restrict__ p, int n) {
    int i = blockIdx.x * 256 + threadIdx.x;
    if (i < n) p[i] = 0.f;
}
__global__ void final_kernel(const float* __restrict__ x, const float* __restrict__ acc,
                             const float* __restrict__ rs, float* __restrict__ out, int n) {
    int i = blockIdx.x * 256 + threadIdx.x;
    if (i < n) out[i] = x[i] + rs[0] * acc[i];
}

// ---------------- launch ----------------
extern "C" void kernel_launch(void* const* d_in, const int* in_sizes, int n_in,
                              void* d_out, int out_size) {
    (void)in_sizes; (void)n_in;
    const float* x        = (const float*)d_in[0];
    const float* cr1_w    = (const float*)d_in[1];
    const float* cr1_b    = (const float*)d_in[2];
    const float* cr2_w    = (const float*)d_in[3];
    const float* cr2_b    = (const float*)d_in[4];
    const float* ln_w     = (const float*)d_in[5];
    const float* ln_b     = (const float*)d_in[6];
    const float* left_w   = (const float*)d_in[7];
    const float* conv1d_w = (const float*)d_in[8];
    const float* conv1d_b = (const float*)d_in[9];
    const float* delta_w  = (const float*)d_in[10];
    const float* delta_b  = (const float*)d_in[11];
    const float* Bp_w     = (const float*)d_in[12];
    const float* Cp_w     = (const float*)d_in[13];
    const float* A_log    = (const float*)d_in[14];
    const float* right_w  = (const float*)d_in[15];
    const float* pn_w     = (const float*)d_in[16];
    const float* pn_b     = (const float*)d_in[17];
    const float* out_w    = (const float*)d_in[18];
    const float* res_scl  = (const float*)d_in[19];
    const float* axis_w   = (const float*)d_in[20];
    float* out = (float*)d_out;

    float *tmp, *x1, *x2, *acc;
    cudaGetSymbolAddress((void**)&tmp, g_tmp);
    cudaGetSymbolAddress((void**)&x1, g_x1);
    cudaGetSymbolAddress((void**)&x2, g_x2);
    cudaGetSymbolAddress((void**)&acc, g_acc);

    cudaFuncSetAttribute(mamba_kernel, cudaFuncAttributeMaxDynamicSharedMemorySize,
                         SMEM_FLOATS * (int)sizeof(float));

    dim3 cg(16, 32, 2);
    conv3d_kernel<<<cg, 256>>>(x, cr1_w, cr1_b, tmp);
    inorm_res_kernel<<<128, 256>>>(tmp, x, x1);
    conv3d_kernel<<<cg, 256>>>(x1, cr2_w, cr2_b, tmp);
    inorm_res_kernel<<<128, 256>>>(tmp, x1, x2);

    zero_kernel<<<(NVOX + 255) / 256, 256>>>(acc, NVOX);

    mamba_kernel<<<dim3(2048, 3), 256, SMEM_FLOATS * (int)sizeof(float)>>>(
        x2, ln_w, ln_b, left_w, conv1d_w, conv1d_b, delta_w, delta_b,
        Bp_w, Cp_w, A_log, right_w, pn_w, pn_b, out_w, axis_w, acc);

    final_kernel<<<(out_size + 255) / 256, 256>>>(x, acc, res_scl, out, out_size);
}

// round 2
// speedup vs baseline: 2.6591x; 2.6591x over previous
#include <cuda_runtime.h>
#include <math.h>

// ---------------- scratch (static device globals; no allocation) ----------------
#define NVOX 4194304  // 2*64*32*32*32
static __device__ float g_tmp[NVOX];
static __device__ float g_x1[NVOX];
static __device__ float g_x2[NVOX];
static __device__ float g_acc[NVOX];

typedef unsigned long long u64t;

// ---------------- f32x2 packed-FMA helpers (Blackwell FFMA2, PTX-only) ----------
__device__ __forceinline__ u64t pk2(float lo, float hi) {
    u64t r; asm("mov.b64 %0, {%1,%2};" : "=l"(r) : "f"(lo), "f"(hi)); return r;
}
__device__ __forceinline__ void upk2(u64t v, float& lo, float& hi) {
    asm("mov.b64 {%0,%1}, %2;" : "=f"(lo), "=f"(hi) : "l"(v));
}
__device__ __forceinline__ u64t fma2(u64t a, u64t b, u64t c) {
    u64t d; asm("fma.rn.f32x2 %0, %1, %2, %3;" : "=l"(d) : "l"(a), "l"(b), "l"(c)); return d;
}

// ---------------- scalar helpers ----------------
__device__ __forceinline__ float softplus_f(float x) {
    return fmaxf(x, 0.f) + log1pf(__expf(-fabsf(x)));
}
__device__ __forceinline__ float silu_f(float x) {
    return x / (1.f + __expf(-x));
}
__device__ __forceinline__ float ex2_fast(float x) {   // MUFU pipe
    float r; asm("ex2.approx.ftz.f32 %0, %1;" : "=f"(r) : "f"(x)); return r;
}

// =================================================================================
// conv3d 3x3x3, C=64->64, +bias. grid (32 h, 16 co-groups of 4, 2 b), block 256.
// smem: weights [ci][kk][pair][2] (6912 f) + input tile [2ci][3][34][34] (6936 f)
// Each thread: lane = d, warp covers 4 w rows, 4 output channels (2 f32x2 pairs).
// =================================================================================
#define CONV_SMEM_BYTES ((6912 + 6936) * 4)
__global__ void __launch_bounds__(256, 4) conv3d_kernel(
    const float* __restrict__ xin, const float* __restrict__ cw,
    const float* __restrict__ cb, float* __restrict__ out)
{
    extern __shared__ float cs[];
    float* WSH = cs;                 // 6912
    float* TIN = cs + 6912;          // 2 * 3468
    const u64t* WSH64 = (const u64t*)WSH;

    int tid = threadIdx.x;
    int lane = tid & 31, wid = tid >> 5;
    int h = blockIdx.x;
    int cog = blockIdx.y;            // co base = cog*4
    int b = blockIdx.z;

    // stage weights: WSH[((ci*27+kk)*2+pp)*2+e] = cw[(cog*4+pp*2+e)*1728 + ci*27 + kk]
    for (int idx = tid; idx < 6912; idx += 256) {
        int e = idx & 1, pp = (idx >> 1) & 1;
        int kk = (idx >> 2) % 27, ci = (idx >> 2) / 27;
        WSH[idx] = cw[(size_t)(cog * 4 + pp * 2 + e) * 1728 + ci * 27 + kk];
    }
    // zero both input tiles (halo cells stay zero forever)
    for (int idx = tid; idx < 6936; idx += 256) TIN[idx] = 0.f;

    u64t acc2[8];
#pragma unroll
    for (int i = 0; i < 8; i++) acc2[i] = 0ULL;

    for (int st = 0; st < 32; st++) {
        __syncthreads();   // previous compute done before overwrite
        // load ci = 2*st, 2*st+1 : interior [kh][w+1][1..32]
#pragma unroll
        for (int r = 0; r < 6; r++) {
            int j = r * 256 + tid;              // 0..1535 float4
            int ci2 = j / 768, rem = j % 768;
            int kh = rem >> 8, q = rem & 255;
            int w = q >> 3, seg = q & 7;
            int hh = h + kh - 1;
            if (hh >= 0 && hh < 32) {
                const float4 v = *(const float4*)(xin +
                    ((size_t)(b * 64 + st * 2 + ci2)) * 32768 + hh * 1024 + w * 32 + seg * 4);
                float* dst = TIN + ci2 * 3468 + kh * 1156 + (w + 1) * 34 + 1 + seg * 4;
                dst[0] = v.x; dst[1] = v.y; dst[2] = v.z; dst[3] = v.w;
            }
        }
        __syncthreads();
#pragma unroll
        for (int ci2 = 0; ci2 < 2; ci2++) {
            int ci = st * 2 + ci2;
            const float* tb = TIN + ci2 * 3468;
            const u64t* wb = WSH64 + ci * 54;          // 27 kk * 2 pairs
#pragma unroll
            for (int kh = 0; kh < 3; kh++) {
                const float* tkh = tb + kh * 1156;
#pragma unroll
                for (int kw = 0; kw < 3; kw++) {
                    u64t wk0 = wb[(kh * 9 + kw * 3 + 0) * 2];
                    u64t wk1 = wb[(kh * 9 + kw * 3 + 0) * 2 + 1];
                    u64t wk2 = wb[(kh * 9 + kw * 3 + 1) * 2];
                    u64t wk3 = wb[(kh * 9 + kw * 3 + 1) * 2 + 1];
                    u64t wk4 = wb[(kh * 9 + kw * 3 + 2) * 2];
                    u64t wk5 = wb[(kh * 9 + kw * 3 + 2) * 2 + 1];
#pragma unroll
                    for (int ws = 0; ws < 4; ws++) {
                        const float* p = tkh + (ws * 8 + wid + kw) * 34 + lane;
                        float v0 = p[0], v1 = p[1], v2 = p[2];
                        u64t vv0 = pk2(v0, v0), vv1 = pk2(v1, v1), vv2 = pk2(v2, v2);
                        acc2[ws * 2]     = fma2(vv0, wk0, acc2[ws * 2]);
                        acc2[ws * 2 + 1] = fma2(vv0, wk1, acc2[ws * 2 + 1]);
                        acc2[ws * 2]     = fma2(vv1, wk2, acc2[ws * 2]);
                        acc2[ws * 2 + 1] = fma2(vv1, wk3, acc2[ws * 2 + 1]);
                        acc2[ws * 2]     = fma2(vv2, wk4, acc2[ws * 2]);
                        acc2[ws * 2 + 1] = fma2(vv2, wk5, acc2[ws * 2 + 1]);
                    }
                }
            }
        }
    }
    float b0 = cb[cog * 4], b1 = cb[cog * 4 + 1], b2 = cb[cog * 4 + 2], b3 = cb[cog * 4 + 3];
#pragma unroll
    for (int ws = 0; ws < 4; ws++) {
        int w = ws * 8 + wid;
        float a0, a1, a2, a3;
        upk2(acc2[ws * 2], a0, a1);
        upk2(acc2[ws * 2 + 1], a2, a3);
        size_t o = ((size_t)(b * 64 + cog * 4)) * 32768 + (size_t)h * 1024 + w * 32 + lane;
        out[o]          = a0 + b0;
        out[o + 32768]  = a1 + b1;
        out[o + 65536]  = a2 + b2;
        out[o + 98304]  = a3 + b3;
    }
}

// ---------------- InstanceNorm3d + LeakyReLU(0.01) + residual (1024 thr) --------
__global__ void inorm_res_kernel(const float* __restrict__ y,
                                 const float* __restrict__ res,
                                 float* __restrict__ out) {
    int bc = blockIdx.x;
    const float4* yp = (const float4*)(y + (size_t)bc * 32768);
    int tid = threadIdx.x;
    int lane = tid & 31, wid = tid >> 5;
    float s1 = 0.f, s2 = 0.f;
    for (int i = tid; i < 8192; i += 1024) {
        float4 v = yp[i];
        s1 += v.x + v.y + v.z + v.w;
        s2 += v.x * v.x + v.y * v.y + v.z * v.z + v.w * v.w;
    }
#pragma unroll
    for (int o = 16; o > 0; o >>= 1) {
        s1 += __shfl_xor_sync(0xffffffffu, s1, o);
        s2 += __shfl_xor_sync(0xffffffffu, s2, o);
    }
    __shared__ float r1[32], r2[32];
    __shared__ float mu_s, rstd_s;
    if (lane == 0) { r1[wid] = s1; r2[wid] = s2; }
    __syncthreads();
    if (tid < 32) {
        float a = r1[tid], c = r2[tid];
#pragma unroll
        for (int o = 16; o > 0; o >>= 1) {
            a += __shfl_xor_sync(0xffffffffu, a, o);
            c += __shfl_xor_sync(0xffffffffu, c, o);
        }
        if (tid == 0) {
            float mu = a * (1.f / 32768.f);
            float var = c * (1.f / 32768.f) - mu * mu;
            mu_s = mu; rstd_s = rsqrtf(var + 1e-5f);
        }
    }
    __syncthreads();
    float mu = mu_s, rstd = rstd_s;
    const float4* rp = (const float4*)(res + (size_t)bc * 32768);
    float4* op = (float4*)(out + (size_t)bc * 32768);
    for (int i = tid; i < 8192; i += 1024) {
        float4 v = yp[i]; float4 r = rp[i]; float4 o; float a;
        a = (v.x - mu) * rstd; o.x = r.x + (a >= 0.f ? a : 0.01f * a);
        a = (v.y - mu) * rstd; o.y = r.y + (a >= 0.f ? a : 0.01f * a);
        a = (v.z - mu) * rstd; o.z = r.z + (a >= 0.f ? a : 0.01f * a);
        a = (v.w - mu) * rstd; o.w = r.w + (a >= 0.f ? a : 0.01f * a);
        op[i] = o;
    }
}

// =================================================================================
// fused per-sequence Mamba, [ch][t] layouts (stride 34), f32x2 GEMMs, ex2 scan.
// grid (2048, 3), block 256. YS aliases DS.
// =================================================================================
#define MB_SMEM_FLOATS 17552
__global__ void __launch_bounds__(256, 3) mamba_kernel(
    const float* __restrict__ xin,
    const float* __restrict__ ln_w,  const float* __restrict__ ln_b,
    const float* __restrict__ left_w, const float* __restrict__ conv1d_w,
    const float* __restrict__ conv1d_b, const float* __restrict__ delta_w,
    const float* __restrict__ delta_b, const float* __restrict__ Bp_w,
    const float* __restrict__ Cp_w,  const float* __restrict__ A_log,
    const float* __restrict__ right_w, const float* __restrict__ pn_w,
    const float* __restrict__ pn_b,  const float* __restrict__ out_w,
    const float* __restrict__ axis_w,
    float* __restrict__ acc_out)
{
    extern __shared__ float sm[];
    float* XS   = sm;            // [64][34]
    float* XL   = sm + 2176;     // [128][34]
    float* DS   = sm + 6528;     // [128][34]  (aliased by YS after scan reads)
    float* GA   = sm + 10880;    // [128][34]
    float* BS   = sm + 15232;    // [16][34]
    float* CS   = sm + 15776;    // [16][34]
    float* MUSD = sm + 16320;    // [64]
    float* A2S  = sm + 16384;    // [16]
    float* LNW  = sm + 16400;    // [64]
    float* LNB  = sm + 16464;    // [64]
    float* CW   = sm + 16528;    // [512]
    float* CB   = sm + 17040;    // [128]
    float* DB   = sm + 17168;    // [128]
    float* PNW  = sm + 17296;    // [128]
    float* PNB  = sm + 17424;    // [128]  -> end 17552
    float* YS   = DS;
    __shared__ float WA;

    int tid = threadIdx.x;
    int q = blockIdx.x;
    int axis = blockIdx.y;

    int b = q >> 10;
    int u = (q >> 5) & 31;
    int v = q & 31;
    long base; int tstride;
    if (axis == 0)      { base = (long)b * 2097152 + u * 32 + v;        tstride = 1024; }
    else if (axis == 1) { base = (long)b * 2097152 + u * 1024 + v;      tstride = 32; }
    else                { base = (long)b * 2097152 + u * 1024 + v * 32; tstride = 1; }

    // ---- phase 0: params + gather (XS[c][t]) ----
    for (int i = tid; i < 64; i += 256) { LNW[i] = ln_w[i]; LNB[i] = ln_b[i]; }
    for (int i = tid; i < 128; i += 256) {
        CB[i] = conv1d_b[i]; DB[i] = delta_b[i]; PNW[i] = pn_w[i]; PNB[i] = pn_b[i];
    }
    for (int i = tid; i < 512; i += 256) CW[i] = conv1d_w[i];
    if (tid < 16) A2S[tid] = -softplus_f(A_log[tid]) * 1.44269504f;   // log2e folded
    if (tid == 0) {
        float a0 = axis_w[0], a1 = axis_w[1], a2 = axis_w[2];
        float m = fmaxf(a0, fmaxf(a1, a2));
        float e0 = __expf(a0 - m), e1 = __expf(a1 - m), e2 = __expf(a2 - m);
        float inv = 1.f / (e0 + e1 + e2);
        WA = (axis == 0 ? e0 : (axis == 1 ? e1 : e2)) * inv;
    }
    for (int e = tid; e < 2048; e += 256) {
        int c = e >> 5, t = e & 31;
        XS[c * 34 + t] = xin[base + (long)c * 32768 + (long)t * tstride];
    }
    __syncthreads();

    // ---- phase 1: layernorm over C=64 per timestep ----
    {
        int t = tid >> 3, g = tid & 7;
        float s1 = 0.f, s2 = 0.f;
#pragma unroll
        for (int cc = 0; cc < 8; cc++) {
            float vv = XS[(g * 8 + cc) * 34 + t];
            s1 += vv; s2 += vv * vv;
        }
#pragma unroll
        for (int o = 4; o > 0; o >>= 1) {
            s1 += __shfl_down_sync(0xffffffffu, s1, o);
            s2 += __shfl_down_sync(0xffffffffu, s2, o);
        }
        if (g == 0) {
            float mu = s1 * (1.f / 64.f);
            float var = s2 * (1.f / 64.f) - mu * mu;
            MUSD[t * 2] = mu;
            MUSD[t * 2 + 1] = rsqrtf(var + 1e-5f);
        }
    }
    __syncthreads();
    for (int e = tid; e < 2048; e += 256) {
        int c = e >> 5, t = e & 31;
        XS[c * 34 + t] = (XS[c * 34 + t] - MUSD[t * 2]) * MUSD[t * 2 + 1] * LNW[c] + LNB[c];
    }
    __syncthreads();

    // ---- phase 2: left/right proj (f32x2); left: causal conv1d(k=4)+silu; right: silu ----
    {
        int col = tid & 127;
        int which = tid >> 7;
        const float4* Wp = (const float4*)((which ? right_w : left_w) + col * 64);
        u64t acc2[16];
#pragma unroll
        for (int j = 0; j < 16; j++) acc2[j] = 0ULL;
        for (int k4 = 0; k4 < 16; k4++) {
            float4 w4 = Wp[k4];
#pragma unroll
            for (int e = 0; e < 4; e++) {
                float wv = (e == 0) ? w4.x : (e == 1) ? w4.y : (e == 2) ? w4.z : w4.w;
                u64t wvv = pk2(wv, wv);
                const u64t* xr = (const u64t*)(XS + (k4 * 4 + e) * 34);
#pragma unroll
                for (int j = 0; j < 16; j++) acc2[j] = fma2(xr[j], wvv, acc2[j]);
            }
        }
        if (which == 0) {
            float c0 = CW[col * 4], c1 = CW[col * 4 + 1], c2 = CW[col * 4 + 2], c3 = CW[col * 4 + 3];
            float bb = CB[col];
            float pm1 = 0.f, pm2 = 0.f, pm3 = 0.f;
#pragma unroll
            for (int j = 0; j < 16; j++) {
                float a0, a1; upk2(acc2[j], a0, a1);
                float s0 = fmaf(c3, a0, bb); s0 = fmaf(c2, pm1, s0);
                s0 = fmaf(c1, pm2, s0); s0 = fmaf(c0, pm3, s0);
                float s1 = fmaf(c3, a1, bb); s1 = fmaf(c2, a0, s1);
                s1 = fmaf(c1, pm1, s1); s1 = fmaf(c0, pm2, s1);
                XL[col * 34 + 2 * j]     = silu_f(s0);
                XL[col * 34 + 2 * j + 1] = silu_f(s1);
                pm3 = pm1; pm2 = a0; pm1 = a1;
            }
        } else {
#pragma unroll
            for (int j = 0; j < 16; j++) {
                float a0, a1; upk2(acc2[j], a0, a1);
                GA[col * 34 + 2 * j]     = silu_f(a0);
                GA[col * 34 + 2 * j + 1] = silu_f(a1);
            }
        }
    }
    __syncthreads();

    // ---- phase 3 (fused): delta proj (+softplus+clip) AND B/C projections ----
    {
        int col = tid & 127, thalf = tid >> 7;
        int jb = thalf * 8;
        int c_bc = tid & 31, sub = tid >> 5;          // sub 0..7; bc t-pairs 2sub, 2sub+1
        const float4* Wd  = (const float4*)(delta_w + col * 128);
        const float4* Wbc = (const float4*)((c_bc < 16 ? Bp_w : Cp_w) + (c_bc & 15) * 128);
        u64t accd[8]; u64t accb0 = 0ULL, accb1 = 0ULL;
#pragma unroll
        for (int j = 0; j < 8; j++) accd[j] = 0ULL;
        for (int k4 = 0; k4 < 32; k4++) {
            float4 wd = Wd[k4];
            float4 wb = Wbc[k4];
#pragma unroll
            for (int e = 0; e < 4; e++) {
                float wdv = (e == 0) ? wd.x : (e == 1) ? wd.y : (e == 2) ? wd.z : wd.w;
                float wbv = (e == 0) ? wb.x : (e == 1) ? wb.y : (e == 2) ? wb.z : wb.w;
                const u64t* xr = (const u64t*)(XL + (k4 * 4 + e) * 34);
                u64t wdd = pk2(wdv, wdv);
#pragma unroll
                for (int j = 0; j < 8; j++) accd[j] = fma2(xr[jb + j], wdd, accd[j]);
                u64t wbb = pk2(wbv, wbv);
                accb0 = fma2(xr[2 * sub],     wbb, accb0);
                accb1 = fma2(xr[2 * sub + 1], wbb, accb1);
            }
        }
        float bb = DB[col];
#pragma unroll
        for (int j = 0; j < 8; j++) {
            float a0, a1; upk2(accd[j], a0, a1);
            int t = thalf * 16 + 2 * j;
            float z0 = softplus_f(a0 + bb);
            float z1 = softplus_f(a1 + bb);
            DS[col * 34 + t]     = fminf(fmaxf(z0, 1e-4f), 10.f);
            DS[col * 34 + t + 1] = fminf(fmaxf(z1, 1e-4f), 10.f);
        }
        float* dst = (c_bc < 16 ? BS : CS) + (c_bc & 15) * 34;
        float bv0, bv1, bv2, bv3;
        upk2(accb0, bv0, bv1); upk2(accb1, bv2, bv3);
        dst[4 * sub]     = bv0;
        dst[4 * sub + 1] = bv1;
        dst[4 * sub + 2] = bv2;
        dst[4 * sub + 3] = bv3;
    }
    __syncthreads();

    // ---- phase 4: selective scan (ex2 on MUFU pipe). pair (i, hlf) owns 8 states ----
    {
        int i = tid >> 1;
        int hlf = tid & 1;
        float h[8], a2l[8];
#pragma unroll
        for (int u2 = 0; u2 < 8; u2++) { h[u2] = 0.f; a2l[u2] = A2S[hlf * 8 + u2]; }
        const float* dsrow = DS + i * 34;
        const float* xlrow = XL + i * 34;
        for (int t = 0; t < 32; t++) {
            float d  = dsrow[t];
            float xv = xlrow[t];
            float dx = d * xv;
            float part = 0.f;
#pragma unroll
            for (int u2 = 0; u2 < 8; u2++) {
                int sidx = hlf * 8 + u2;
                float e = ex2_fast(d * a2l[u2]);
                h[u2] = fmaf(e, h[u2], dx * BS[sidx * 34 + t]);
                part = fmaf(h[u2], CS[sidx * 34 + t], part);
            }
            part += __shfl_xor_sync(0xffffffffu, part, 1);
            if (hlf == 0) YS[i * 34 + t] = part;   // overwrites DS[i][t], already consumed
        }
    }
    __syncthreads();

    // ---- phase 5: gate, then layernorm over di=128 per timestep ----
    for (int e = tid; e < 4096; e += 256) {
        int i = e >> 5, t = e & 31;
        YS[i * 34 + t] *= GA[i * 34 + t];
    }
    __syncthreads();
    {
        int t = tid >> 3, g = tid & 7;
        float s1 = 0.f, s2 = 0.f;
#pragma unroll
        for (int m = 0; m < 16; m++) {
            float vv = YS[(g + m * 8) * 34 + t];
            s1 += vv; s2 += vv * vv;
        }
#pragma unroll
        for (int o = 4; o > 0; o >>= 1) {
            s1 += __shfl_down_sync(0xffffffffu, s1, o);
            s2 += __shfl_down_sync(0xffffffffu, s2, o);
        }
        if (g == 0) {
            float mu = s1 * (1.f / 128.f);
            float var = s2 * (1.f / 128.f) - mu * mu;
            MUSD[t * 2] = mu;
            MUSD[t * 2 + 1] = rsqrtf(var + 1e-5f);
        }
    }
    __syncthreads();
    for (int e = tid; e < 4096; e += 256) {
        int i = e >> 5, t = e & 31;
        YS[i * 34 + t] = (YS[i * 34 + t] - MUSD[t * 2]) * MUSD[t * 2 + 1] * PNW[i] + PNB[i];
    }
    __syncthreads();

    // ---- phase 6: out projection [32,128]x[128,64] + weighted atomic scatter ----
    {
        int col = tid & 63, tq = tid >> 6;
        const float4* Wp = (const float4*)(out_w + col * 128);
        u64t acc2[4];
#pragma unroll
        for (int j = 0; j < 4; j++) acc2[j] = 0ULL;
        for (int k4 = 0; k4 < 32; k4++) {
            float4 w4 = Wp[k4];
#pragma unroll
            for (int e = 0; e < 4; e++) {
                float wv = (e == 0) ? w4.x : (e == 1) ? w4.y : (e == 2) ? w4.z : w4.w;
                u64t wvv = pk2(wv, wv);
                const u64t* xr = (const u64t*)(YS + (k4 * 4 + e) * 34) + tq * 4;
#pragma unroll
                for (int j = 0; j < 4; j++) acc2[j] = fma2(xr[j], wvv, acc2[j]);
            }
        }
        float wa = WA;
#pragma unroll
        for (int j = 0; j < 4; j++) {
            float a0, a1; upk2(acc2[j], a0, a1);
            int t = tq * 8 + 2 * j;
            atomicAdd(&acc_out[base + (long)col * 32768 + (long)t * tstride],       wa * a0);
            atomicAdd(&acc_out[base + (long)col * 32768 + (long)(t + 1) * tstride], wa * a1);
        }
    }
}

// ---------------- misc ----------------
__global__ void zero_kernel(float4* __restrict__ p, int n4) {
    int i = blockIdx.x * 256 + threadIdx.x;
    if (i < n4) p[i] = make_float4(0.f, 0.f, 0.f, 0.f);
}
__global__ void final_kernel(const float4* __restrict__ x, const float4* __restrict__ acc,
                             const float* __restrict__ rs, float4* __restrict__ out, int n4) {
    int i = blockIdx.x * 256 + threadIdx.x;
    if (i < n4) {
        float s = rs[0];
        float4 a = x[i], c = acc[i];
        out[i] = make_float4(fmaf(s, c.x, a.x), fmaf(s, c.y, a.y),
                             fmaf(s, c.z, a.z), fmaf(s, c.w, a.w));
    }
}

// ---------------- launch ----------------
extern "C" void kernel_launch(void* const* d_in, const int* in_sizes, int n_in,
                              void* d_out, int out_size) {
    (void)in_sizes; (void)n_in;
    const float* x        = (const float*)d_in[0];
    const float* cr1_w    = (const float*)d_in[1];
    const float* cr1_b    = (const float*)d_in[2];
    const float* cr2_w    = (const float*)d_in[3];
    const float* cr2_b    = (const float*)d_in[4];
    const float* ln_w     = (const float*)d_in[5];
    const float* ln_b     = (const float*)d_in[6];
    const float* left_w   = (const float*)d_in[7];
    const float* conv1d_w = (const float*)d_in[8];
    const float* conv1d_b = (const float*)d_in[9];
    const float* delta_w  = (const float*)d_in[10];
    const float* delta_b  = (const float*)d_in[11];
    const float* Bp_w     = (const float*)d_in[12];
    const float* Cp_w     = (const float*)d_in[13];
    const float* A_log    = (const float*)d_in[14];
    const float* right_w  = (const float*)d_in[15];
    const float* pn_w     = (const float*)d_in[16];
    const float* pn_b     = (const float*)d_in[17];
    const float* out_w    = (const float*)d_in[18];
    const float* res_scl  = (const float*)d_in[19];
    const float* axis_w   = (const float*)d_in[20];
    float* out = (float*)d_out;

    float *tmp, *x1, *x2, *acc;
    cudaGetSymbolAddress((void**)&tmp, g_tmp);
    cudaGetSymbolAddress((void**)&x1, g_x1);
    cudaGetSymbolAddress((void**)&x2, g_x2);
    cudaGetSymbolAddress((void**)&acc, g_acc);

    cudaFuncSetAttribute(conv3d_kernel, cudaFuncAttributeMaxDynamicSharedMemorySize,
                         CONV_SMEM_BYTES);
    cudaFuncSetAttribute(mamba_kernel, cudaFuncAttributeMaxDynamicSharedMemorySize,
                         MB_SMEM_FLOATS * (int)sizeof(float));

    dim3 cg(32, 16, 2);
    conv3d_kernel<<<cg, 256, CONV_SMEM_BYTES>>>(x, cr1_w, cr1_b, tmp);
    inorm_res_kernel<<<128, 1024>>>(tmp, x, x1);
    conv3d_kernel<<<cg, 256, CONV_SMEM_BYTES>>>(x1, cr2_w, cr2_b, tmp);
    inorm_res_kernel<<<128, 1024>>>(tmp, x1, x2);

    zero_kernel<<<(NVOX / 4 + 255) / 256, 256>>>((float4*)acc, NVOX / 4);

    mamba_kernel<<<dim3(2048, 3), 256, MB_SMEM_FLOATS * (int)sizeof(float)>>>(
        x2, ln_w, ln_b, left_w, conv1d_w, conv1d_b, delta_w, delta_b,
        Bp_w, Cp_w, A_log, right_w, pn_w, pn_b, out_w, axis_w, acc);

    final_kernel<<<(out_size / 4 + 255) / 256, 256>>>(
        (const float4*)x, (const float4*)acc, res_scl, (float4*)out, out_size / 4);
}

// round 3
// speedup vs baseline: 3.0180x; 1.1350x over previous
#include <cuda_runtime.h>
#include <math.h>

// ---------------- scratch (static device globals; no allocation) ----------------
#define NVOX 4194304  // 2*64*32*32*32
static __device__ float g_tmp[NVOX];
static __device__ float g_x1[NVOX];
static __device__ float g_x2[NVOX];
static __device__ float g_acc[NVOX];

typedef unsigned long long u64t;

// ---------------- f32x2 packed-FMA helpers (Blackwell FFMA2, PTX-only) ----------
__device__ __forceinline__ u64t pk2(float lo, float hi) {
    u64t r; asm("mov.b64 %0, {%1,%2};" : "=l"(r) : "f"(lo), "f"(hi)); return r;
}
__device__ __forceinline__ void upk2(u64t v, float& lo, float& hi) {
    asm("mov.b64 {%0,%1}, %2;" : "=f"(lo), "=f"(hi) : "l"(v));
}
__device__ __forceinline__ u64t fma2(u64t a, u64t b, u64t c) {
    u64t d; asm("fma.rn.f32x2 %0, %1, %2, %3;" : "=l"(d) : "l"(a), "l"(b), "l"(c)); return d;
}

// ---------------- scalar helpers ----------------
__device__ __forceinline__ float softplus_f(float x) {
    return fmaxf(x, 0.f) + log1pf(__expf(-fabsf(x)));
}
__device__ __forceinline__ float silu_f(float x) {
    return x / (1.f + __expf(-x));
}
__device__ __forceinline__ float ex2_fast(float x) {   // MUFU pipe
    float r; asm("ex2.approx.ftz.f32 %0, %1;" : "=f"(r) : "f"(x)); return r;
}

// =================================================================================
// conv3d 3x3x3, C=64->64, +bias. grid (32 h, 8 co-groups of 8, 2 b), block 256.
// smem: weights [ci][kk][4 pairs][2] (13824 f) + input tile [3][34][34] (3468 f)
// Each thread: lane = d, warp covers 4 w rows (stride 8), 8 output channels.
// LDS:FMA2 per (ci,kh,kw): (12 row + 12 wgt) : 48  -> FMA-pipe bound.
// =================================================================================
#define CONV_SMEM_BYTES ((13824 + 3468) * 4)
__global__ void __launch_bounds__(256, 3) conv3d_kernel(
    const float* __restrict__ xin, const float* __restrict__ cw,
    const float* __restrict__ cb, float* __restrict__ out)
{
    extern __shared__ float cs[];
    float* WSH = cs;                 // 13824
    float* TIN = cs + 13824;         // 3468
    const u64t* WSH64 = (const u64t*)WSH;

    int tid = threadIdx.x;
    int lane = tid & 31, wid = tid >> 5;
    int h = blockIdx.x;
    int cog = blockIdx.y;            // co base = cog*8
    int b = blockIdx.z;

    // stage weights: float idx = (ci*27+kk)*8 + p*2 + e
    for (int idx = tid; idx < 13824; idx += 256) {
        int e = idx & 1, p = (idx >> 1) & 3;
        int kk = (idx >> 3) % 27, ci = (idx >> 3) / 27;
        WSH[idx] = cw[(size_t)(cog * 8 + p * 2 + e) * 1728 + ci * 27 + kk];
    }
    // zero input tile (halo cells stay zero forever; (h,kh) validity is ci-invariant)
    for (int idx = tid; idx < 3468; idx += 256) TIN[idx] = 0.f;

    u64t acc2[16];
#pragma unroll
    for (int i = 0; i < 16; i++) acc2[i] = 0ULL;

    for (int ci = 0; ci < 64; ci++) {
        __syncthreads();   // previous compute done before overwrite
        // load interior [kh][w+1][1..32] : 768 float4, 3 per thread
#pragma unroll
        for (int r = 0; r < 3; r++) {
            int j = r * 256 + tid;              // 0..767
            int kh = j >> 8, q = j & 255;
            int w = q >> 3, seg = q & 7;
            int hh = h + kh - 1;
            if (hh >= 0 && hh < 32) {
                const float4 v = *(const float4*)(xin +
                    ((size_t)(b * 64 + ci)) * 32768 + hh * 1024 + w * 32 + seg * 4);
                float* dst = TIN + kh * 1156 + (w + 1) * 34 + 1 + seg * 4;
                dst[0] = v.x; dst[1] = v.y; dst[2] = v.z; dst[3] = v.w;
            }
        }
        __syncthreads();
        const u64t* wb = WSH64 + ci * 108;
#pragma unroll
        for (int kh = 0; kh < 3; kh++) {
            const float* tkh = TIN + kh * 1156;
#pragma unroll
            for (int kw = 0; kw < 3; kw++) {
                u64t wk[3][4];
#pragma unroll
                for (int kd = 0; kd < 3; kd++)
#pragma unroll
                    for (int p = 0; p < 4; p++)
                        wk[kd][p] = wb[(kh * 9 + kw * 3 + kd) * 4 + p];
#pragma unroll
                for (int ws = 0; ws < 4; ws++) {
                    const float* p0 = tkh + (ws * 8 + wid + kw) * 34 + lane;
                    float v0 = p0[0], v1 = p0[1], v2 = p0[2];
                    u64t vv0 = pk2(v0, v0), vv1 = pk2(v1, v1), vv2 = pk2(v2, v2);
#pragma unroll
                    for (int p = 0; p < 4; p++) {
                        acc2[ws * 4 + p] = fma2(vv0, wk[0][p], acc2[ws * 4 + p]);
                        acc2[ws * 4 + p] = fma2(vv1, wk[1][p], acc2[ws * 4 + p]);
                        acc2[ws * 4 + p] = fma2(vv2, wk[2][p], acc2[ws * 4 + p]);
                    }
                }
            }
        }
    }
    float bias[8];
#pragma unroll
    for (int e = 0; e < 8; e++) bias[e] = cb[cog * 8 + e];
#pragma unroll
    for (int ws = 0; ws < 4; ws++) {
        int w = ws * 8 + wid;
        size_t o = ((size_t)(b * 64 + cog * 8)) * 32768 + (size_t)h * 1024 + w * 32 + lane;
#pragma unroll
        for (int p = 0; p < 4; p++) {
            float alo, ahi;
            upk2(acc2[ws * 4 + p], alo, ahi);
            out[o + (size_t)(p * 2) * 32768]     = alo + bias[p * 2];
            out[o + (size_t)(p * 2 + 1) * 32768] = ahi + bias[p * 2 + 1];
        }
    }
}

// ---------------- InstanceNorm3d + LeakyReLU(0.01) + residual (1024 thr) --------
__global__ void inorm_res_kernel(const float* __restrict__ y,
                                 const float* __restrict__ res,
                                 float* __restrict__ out) {
    int bc = blockIdx.x;
    const float4* yp = (const float4*)(y + (size_t)bc * 32768);
    int tid = threadIdx.x;
    int lane = tid & 31, wid = tid >> 5;
    float s1 = 0.f, s2 = 0.f;
    for (int i = tid; i < 8192; i += 1024) {
        float4 v = yp[i];
        s1 += v.x + v.y + v.z + v.w;
        s2 += v.x * v.x + v.y * v.y + v.z * v.z + v.w * v.w;
    }
#pragma unroll
    for (int o = 16; o > 0; o >>= 1) {
        s1 += __shfl_xor_sync(0xffffffffu, s1, o);
        s2 += __shfl_xor_sync(0xffffffffu, s2, o);
    }
    __shared__ float r1[32], r2[32];
    __shared__ float mu_s, rstd_s;
    if (lane == 0) { r1[wid] = s1; r2[wid] = s2; }
    __syncthreads();
    if (tid < 32) {
        float a = r1[tid], c = r2[tid];
#pragma unroll
        for (int o = 16; o > 0; o >>= 1) {
            a += __shfl_xor_sync(0xffffffffu, a, o);
            c += __shfl_xor_sync(0xffffffffu, c, o);
        }
        if (tid == 0) {
            float mu = a * (1.f / 32768.f);
            float var = c * (1.f / 32768.f) - mu * mu;
            mu_s = mu; rstd_s = rsqrtf(var + 1e-5f);
        }
    }
    __syncthreads();
    float mu = mu_s, rstd = rstd_s;
    const float4* rp = (const float4*)(res + (size_t)bc * 32768);
    float4* op = (float4*)(out + (size_t)bc * 32768);
    for (int i = tid; i < 8192; i += 1024) {
        float4 v = yp[i]; float4 r = rp[i]; float4 o; float a;
        a = (v.x - mu) * rstd; o.x = r.x + (a >= 0.f ? a : 0.01f * a);
        a = (v.y - mu) * rstd; o.y = r.y + (a >= 0.f ? a : 0.01f * a);
        a = (v.z - mu) * rstd; o.z = r.z + (a >= 0.f ? a : 0.01f * a);
        a = (v.w - mu) * rstd; o.w = r.w + (a >= 0.f ? a : 0.01f * a);
        op[i] = o;
    }
}

// =================================================================================
// fused per-sequence Mamba, [ch][t] layouts (stride 34), col-paired f32x2 GEMMs.
// grid (2048, 3), block 256. YS aliases DS.
// =================================================================================
#define MB_SMEM_FLOATS 17552
__global__ void __launch_bounds__(256, 3) mamba_kernel(
    const float* __restrict__ xin,
    const float* __restrict__ ln_w,  const float* __restrict__ ln_b,
    const float* __restrict__ left_w, const float* __restrict__ conv1d_w,
    const float* __restrict__ conv1d_b, const float* __restrict__ delta_w,
    const float* __restrict__ delta_b, const float* __restrict__ Bp_w,
    const float* __restrict__ Cp_w,  const float* __restrict__ A_log,
    const float* __restrict__ right_w, const float* __restrict__ pn_w,
    const float* __restrict__ pn_b,  const float* __restrict__ out_w,
    const float* __restrict__ axis_w,
    float* __restrict__ acc_out)
{
    extern __shared__ float sm[];
    float* XS   = sm;            // [64][34]
    float* XL   = sm + 2176;     // [128][34]  left post conv+silu
    float* DS   = sm + 6528;     // [128][34]  raw left proj -> delta -> YS
    float* GA   = sm + 10880;    // [128][34]  raw right proj -> gate
    float* BS   = sm + 15232;    // [16][34]
    float* CS   = sm + 15776;    // [16][34]
    float* MUSD = sm + 16320;    // [64]
    float* A2S  = sm + 16384;    // [16]
    float* LNW  = sm + 16400;    // [64]
    float* LNB  = sm + 16464;    // [64]
    float* CW   = sm + 16528;    // [512]
    float* CB   = sm + 17040;    // [128]
    float* DB   = sm + 17168;    // [128]
    float* PNW  = sm + 17296;    // [128]
    float* PNB  = sm + 17424;    // [128]  -> end 17552
    float* YS   = DS;
    __shared__ float WA;

    int tid = threadIdx.x;
    int q = blockIdx.x;
    int axis = blockIdx.y;

    int b = q >> 10;
    int u = (q >> 5) & 31;
    int v = q & 31;
    long base; int tstride;
    if (axis == 0)      { base = (long)b * 2097152 + u * 32 + v;        tstride = 1024; }
    else if (axis == 1) { base = (long)b * 2097152 + u * 1024 + v;      tstride = 32; }
    else                { base = (long)b * 2097152 + u * 1024 + v * 32; tstride = 1; }

    // ---- phase 0: params + gather (XS[c][t]) ----
    for (int i = tid; i < 64; i += 256) { LNW[i] = ln_w[i]; LNB[i] = ln_b[i]; }
    for (int i = tid; i < 128; i += 256) {
        CB[i] = conv1d_b[i]; DB[i] = delta_b[i]; PNW[i] = pn_w[i]; PNB[i] = pn_b[i];
    }
    for (int i = tid; i < 512; i += 256) CW[i] = conv1d_w[i];
    if (tid < 16) A2S[tid] = -softplus_f(A_log[tid]) * 1.44269504f;   // log2e folded
    if (tid == 0) {
        float a0 = axis_w[0], a1 = axis_w[1], a2 = axis_w[2];
        float m = fmaxf(a0, fmaxf(a1, a2));
        float e0 = __expf(a0 - m), e1 = __expf(a1 - m), e2 = __expf(a2 - m);
        float inv = 1.f / (e0 + e1 + e2);
        WA = (axis == 0 ? e0 : (axis == 1 ? e1 : e2)) * inv;
    }
    for (int e = tid; e < 2048; e += 256) {
        int c = e >> 5, t = e & 31;
        XS[c * 34 + t] = xin[base + (long)c * 32768 + (long)t * tstride];
    }
    __syncthreads();

    // ---- phase 1: layernorm over C=64 per timestep ----
    {
        int t = tid >> 3, g = tid & 7;
        float s1 = 0.f, s2 = 0.f;
#pragma unroll
        for (int cc = 0; cc < 8; cc++) {
            float vv = XS[(g * 8 + cc) * 34 + t];
            s1 += vv; s2 += vv * vv;
        }
#pragma unroll
        for (int o = 4; o > 0; o >>= 1) {
            s1 += __shfl_down_sync(0xffffffffu, s1, o);
            s2 += __shfl_down_sync(0xffffffffu, s2, o);
        }
        if (g == 0) {
            float mu = s1 * (1.f / 64.f);
            float var = s2 * (1.f / 64.f) - mu * mu;
            MUSD[t * 2] = mu;
            MUSD[t * 2 + 1] = rsqrtf(var + 1e-5f);
        }
    }
    __syncthreads();
    for (int e = tid; e < 2048; e += 256) {
        int c = e >> 5, t = e & 31;
        XS[c * 34 + t] = (XS[c * 34 + t] - MUSD[t * 2]) * MUSD[t * 2 + 1] * LNW[c] + LNB[c];
    }
    __syncthreads();

    // ---- phase 2: left/right raw projections, 2 cols/thread share xr loads ----
    {
        int pairidx = tid & 63;
        int half = (tid >> 6) & 1;          // t-half: 8 u64
        int which = tid >> 7;               // 0: left->DS, 1: right->GA
        int c0 = pairidx * 2;
        const float4* Wp0 = (const float4*)((which ? right_w : left_w) + c0 * 64);
        const float4* Wp1 = (const float4*)((which ? right_w : left_w) + (c0 + 1) * 64);
        u64t accA[8], accB[8];
#pragma unroll
        for (int j = 0; j < 8; j++) { accA[j] = 0ULL; accB[j] = 0ULL; }
        for (int k4 = 0; k4 < 16; k4++) {
            float4 wa4 = Wp0[k4];
            float4 wb4 = Wp1[k4];
#pragma unroll
            for (int e = 0; e < 4; e++) {
                float wa = (e == 0) ? wa4.x : (e == 1) ? wa4.y : (e == 2) ? wa4.z : wa4.w;
                float wb = (e == 0) ? wb4.x : (e == 1) ? wb4.y : (e == 2) ? wb4.z : wb4.w;
                u64t waa = pk2(wa, wa), wbb = pk2(wb, wb);
                const u64t* xr = (const u64t*)(XS + (k4 * 4 + e) * 34) + half * 8;
#pragma unroll
                for (int j = 0; j < 8; j++) {
                    u64t xv = xr[j];
                    accA[j] = fma2(xv, waa, accA[j]);
                    accB[j] = fma2(xv, wbb, accB[j]);
                }
            }
        }
        float* dstbase = which ? GA : DS;
        u64t* dA = (u64t*)(dstbase + c0 * 34) + half * 8;
        u64t* dB = (u64t*)(dstbase + (c0 + 1) * 34) + half * 8;
#pragma unroll
        for (int j = 0; j < 8; j++) { dA[j] = accA[j]; dB[j] = accB[j]; }
    }
    __syncthreads();

    // ---- phase 2b: causal conv1d(k=4)+silu on left (DS->XL); silu gate in-place ----
    {
        int col = tid >> 1, half = tid & 1;
        int t0 = half * 16;
        float c0 = CW[col * 4], c1 = CW[col * 4 + 1], c2 = CW[col * 4 + 2], c3 = CW[col * 4 + 3];
        float bb = CB[col];
        const float* P = DS + col * 34;
        float* XLr = XL + col * 34;
        float* GAr = GA + col * 34;
#pragma unroll
        for (int dt = 0; dt < 16; dt++) {
            int t = t0 + dt;
            float s = fmaf(c3, P[t], bb);
            if (t >= 1) s = fmaf(c2, P[t - 1], s);
            if (t >= 2) s = fmaf(c1, P[t - 2], s);
            if (t >= 3) s = fmaf(c0, P[t - 3], s);
            XLr[t] = silu_f(s);
            GAr[t] = silu_f(GAr[t]);
        }
    }
    __syncthreads();

    // ---- phase 3: delta (2 cols/thread, 128 thr) + fused B/C (128 thr) ----
    if (tid < 128) {
        int pairidx = tid & 63;
        int half = tid >> 6;
        int c0 = pairidx * 2;
        const float4* Wp0 = (const float4*)(delta_w + c0 * 128);
        const float4* Wp1 = (const float4*)(delta_w + (c0 + 1) * 128);
        u64t accA[8], accB[8];
#pragma unroll
        for (int j = 0; j < 8; j++) { accA[j] = 0ULL; accB[j] = 0ULL; }
        for (int k4 = 0; k4 < 32; k4++) {
            float4 wa4 = Wp0[k4];
            float4 wb4 = Wp1[k4];
#pragma unroll
            for (int e = 0; e < 4; e++) {
                float wa = (e == 0) ? wa4.x : (e == 1) ? wa4.y : (e == 2) ? wa4.z : wa4.w;
                float wb = (e == 0) ? wb4.x : (e == 1) ? wb4.y : (e == 2) ? wb4.z : wb4.w;
                u64t waa = pk2(wa, wa), wbb = pk2(wb, wb);
                const u64t* xr = (const u64t*)(XL + (k4 * 4 + e) * 34) + half * 8;
#pragma unroll
                for (int j = 0; j < 8; j++) {
                    u64t xv = xr[j];
                    accA[j] = fma2(xv, waa, accA[j]);
                    accB[j] = fma2(xv, wbb, accB[j]);
                }
            }
        }
        float b0 = DB[c0], b1 = DB[c0 + 1];
        float* d0 = DS + c0 * 34 + half * 16;
        float* d1 = DS + (c0 + 1) * 34 + half * 16;
#pragma unroll
        for (int j = 0; j < 8; j++) {
            float a0, a1; upk2(accA[j], a0, a1);
            d0[2 * j]     = fminf(fmaxf(softplus_f(a0 + b0), 1e-4f), 10.f);
            d0[2 * j + 1] = fminf(fmaxf(softplus_f(a1 + b0), 1e-4f), 10.f);
            upk2(accB[j], a0, a1);
            d1[2 * j]     = fminf(fmaxf(softplus_f(a0 + b1), 1e-4f), 10.f);
            d1[2 * j + 1] = fminf(fmaxf(softplus_f(a1 + b1), 1e-4f), 10.f);
        }
    } else {
        int s = tid & 15;
        int seg = (tid >> 4) & 7;           // 2 u64 = 4 timesteps
        const float4* Wb = (const float4*)(Bp_w + s * 128);
        const float4* Wc = (const float4*)(Cp_w + s * 128);
        u64t b0a = 0ULL, b1a = 0ULL, c0a = 0ULL, c1a = 0ULL;
        for (int k4 = 0; k4 < 32; k4++) {
            float4 wb4 = Wb[k4];
            float4 wc4 = Wc[k4];
#pragma unroll
            for (int e = 0; e < 4; e++) {
                float wb = (e == 0) ? wb4.x : (e == 1) ? wb4.y : (e == 2) ? wb4.z : wb4.w;
                float wc = (e == 0) ? wc4.x : (e == 1) ? wc4.y : (e == 2) ? wc4.z : wc4.w;
                u64t wbb = pk2(wb, wb), wcc = pk2(wc, wc);
                const u64t* xr = (const u64t*)(XL + (k4 * 4 + e) * 34) + seg * 2;
                u64t x0 = xr[0], x1 = xr[1];
                b0a = fma2(x0, wbb, b0a); b1a = fma2(x1, wbb, b1a);
                c0a = fma2(x0, wcc, c0a); c1a = fma2(x1, wcc, c1a);
            }
        }
        u64t* bd = (u64t*)(BS + s * 34) + seg * 2;
        u64t* cd = (u64t*)(CS + s * 34) + seg * 2;
        bd[0] = b0a; bd[1] = b1a;
        cd[0] = c0a; cd[1] = c1a;
    }
    __syncthreads();

    // ---- phase 4: selective scan (ex2 on MUFU). pair (i, hlf) owns 8 states ----
    {
        int i = tid >> 1;
        int hlf = tid & 1;
        float h[8], a2l[8];
#pragma unroll
        for (int u2 = 0; u2 < 8; u2++) { h[u2] = 0.f; a2l[u2] = A2S[hlf * 8 + u2]; }
        const float* dsrow = DS + i * 34;
        const float* xlrow = XL + i * 34;
        for (int t = 0; t < 32; t++) {
            float d  = dsrow[t];
            float xv = xlrow[t];
            float dx = d * xv;
            float part = 0.f;
#pragma unroll
            for (int u2 = 0; u2 < 8; u2++) {
                int sidx = hlf * 8 + u2;
                float e = ex2_fast(d * a2l[u2]);
                h[u2] = fmaf(e, h[u2], dx * BS[sidx * 34 + t]);
                part = fmaf(h[u2], CS[sidx * 34 + t], part);
            }
            part += __shfl_xor_sync(0xffffffffu, part, 1);
            if (hlf == 0) YS[i * 34 + t] = part;   // overwrites DS[i][t], already consumed
        }
    }
    __syncthreads();

    // ---- phase 5: gate, then layernorm over di=128 per timestep ----
    for (int e = tid; e < 4096; e += 256) {
        int i = e >> 5, t = e & 31;
        YS[i * 34 + t] *= GA[i * 34 + t];
    }
    __syncthreads();
    {
        int t = tid >> 3, g = tid & 7;
        float s1 = 0.f, s2 = 0.f;
#pragma unroll
        for (int m = 0; m < 16; m++) {
            float vv = YS[(g + m * 8) * 34 + t];
            s1 += vv; s2 += vv * vv;
        }
#pragma unroll
        for (int o = 4; o > 0; o >>= 1) {
            s1 += __shfl_down_sync(0xffffffffu, s1, o);
            s2 += __shfl_down_sync(0xffffffffu, s2, o);
        }
        if (g == 0) {
            float mu = s1 * (1.f / 128.f);
            float var = s2 * (1.f / 128.f) - mu * mu;
            MUSD[t * 2] = mu;
            MUSD[t * 2 + 1] = rsqrtf(var + 1e-5f);
        }
    }
    __syncthreads();
    for (int e = tid; e < 4096; e += 256) {
        int i = e >> 5, t = e & 31;
        YS[i * 34 + t] = (YS[i * 34 + t] - MUSD[t * 2]) * MUSD[t * 2 + 1] * PNW[i] + PNB[i];
    }
    __syncthreads();

    // ---- phase 6: out projection (2 cols/thread) + weighted atomic scatter ----
    if (tid < 128) {
        int cp = tid & 31;                  // col pair
        int jq = (tid >> 5) & 3;            // 4 u64 = 8 timesteps
        int c0 = cp * 2;
        const float4* Wp0 = (const float4*)(out_w + c0 * 128);
        const float4* Wp1 = (const float4*)(out_w + (c0 + 1) * 128);
        u64t accA[4], accB[4];
#pragma unroll
        for (int j = 0; j < 4; j++) { accA[j] = 0ULL; accB[j] = 0ULL; }
        for (int k4 = 0; k4 < 32; k4++) {
            float4 wa4 = Wp0[k4];
            float4 wb4 = Wp1[k4];
#pragma unroll
            for (int e = 0; e < 4; e++) {
                float wa = (e == 0) ? wa4.x : (e == 1) ? wa4.y : (e == 2) ? wa4.z : wa4.w;
                float wb = (e == 0) ? wb4.x : (e == 1) ? wb4.y : (e == 2) ? wb4.z : wb4.w;
                u64t waa = pk2(wa, wa), wbb = pk2(wb, wb);
                const u64t* xr = (const u64t*)(YS + (k4 * 4 + e) * 34) + jq * 4;
#pragma unroll
                for (int j = 0; j < 4; j++) {
                    u64t xv = xr[j];
                    accA[j] = fma2(xv, waa, accA[j]);
                    accB[j] = fma2(xv, wbb, accB[j]);
                }
            }
        }
        float wa = WA;
#pragma unroll
        for (int j = 0; j < 4; j++) {
            int t = jq * 8 + 2 * j;
            float a0, a1; upk2(accA[j], a0, a1);
            atomicAdd(&acc_out[base + (long)c0 * 32768 + (long)t * tstride],       wa * a0);
            atomicAdd(&acc_out[base + (long)c0 * 32768 + (long)(t + 1) * tstride], wa * a1);
            upk2(accB[j], a0, a1);
            atomicAdd(&acc_out[base + (long)(c0 + 1) * 32768 + (long)t * tstride],       wa * a0);
            atomicAdd(&acc_out[base + (long)(c0 + 1) * 32768 + (long)(t + 1) * tstride], wa * a1);
        }
    }
}

// ---------------- misc ----------------
__global__ void zero_kernel(float4* __restrict__ p, int n4) {
    int i = blockIdx.x * 256 + threadIdx.x;
    if (i < n4) p[i] = make_float4(0.f, 0.f, 0.f, 0.f);
}
__global__ void final_kernel(const float4* __restrict__ x, const float4* __restrict__ acc,
                             const float* __restrict__ rs, float4* __restrict__ out, int n4) {
    int i = blockIdx.x * 256 + threadIdx.x;
    if (i < n4) {
        float s = rs[0];
        float4 a = x[i], c = acc[i];
        out[i] = make_float4(fmaf(s, c.x, a.x), fmaf(s, c.y, a.y),
                             fmaf(s, c.z, a.z), fmaf(s, c.w, a.w));
    }
}

// ---------------- launch ----------------
extern "C" void kernel_launch(void* const* d_in, const int* in_sizes, int n_in,
                              void* d_out, int out_size) {
    (void)in_sizes; (void)n_in;
    const float* x        = (const float*)d_in[0];
    const float* cr1_w    = (const float*)d_in[1];
    const float* cr1_b    = (const float*)d_in[2];
    const float* cr2_w    = (const float*)d_in[3];
    const float* cr2_b    = (const float*)d_in[4];
    const float* ln_w     = (const float*)d_in[5];
    const float* ln_b     = (const float*)d_in[6];
    const float* left_w   = (const float*)d_in[7];
    const float* conv1d_w = (const float*)d_in[8];
    const float* conv1d_b = (const float*)d_in[9];
    const float* delta_w  = (const float*)d_in[10];
    const float* delta_b  = (const float*)d_in[11];
    const float* Bp_w     = (const float*)d_in[12];
    const float* Cp_w     = (const float*)d_in[13];
    const float* A_log    = (const float*)d_in[14];
    const float* right_w  = (const float*)d_in[15];
    const float* pn_w     = (const float*)d_in[16];
    const float* pn_b     = (const float*)d_in[17];
    const float* out_w    = (const float*)d_in[18];
    const float* res_scl  = (const float*)d_in[19];
    const float* axis_w   = (const float*)d_in[20];
    float* out = (float*)d_out;

    float *tmp, *x1, *x2, *acc;
    cudaGetSymbolAddress((void**)&tmp, g_tmp);
    cudaGetSymbolAddress((void**)&x1, g_x1);
    cudaGetSymbolAddress((void**)&x2, g_x2);
    cudaGetSymbolAddress((void**)&acc, g_acc);

    cudaFuncSetAttribute(conv3d_kernel, cudaFuncAttributeMaxDynamicSharedMemorySize,
                         CONV_SMEM_BYTES);
    cudaFuncSetAttribute(mamba_kernel, cudaFuncAttributeMaxDynamicSharedMemorySize,
                         MB_SMEM_FLOATS * (int)sizeof(float));

    // zero first so mamba lands on ncu's -s 5 slot
    zero_kernel<<<(NVOX / 4 + 255) / 256, 256>>>((float4*)acc, NVOX / 4);

    dim3 cg(32, 8, 2);
    conv3d_kernel<<<cg, 256, CONV_SMEM_BYTES>>>(x, cr1_w, cr1_b, tmp);
    inorm_res_kernel<<<128, 1024>>>(tmp, x, x1);
    conv3d_kernel<<<cg, 256, CONV_SMEM_BYTES>>>(x1, cr2_w, cr2_b, tmp);
    inorm_res_kernel<<<128, 1024>>>(tmp, x1, x2);

    mamba_kernel<<<dim3(2048, 3), 256, MB_SMEM_FLOATS * (int)sizeof(float)>>>(
        x2, ln_w, ln_b, left_w, conv1d_w, conv1d_b, delta_w, delta_b,
        Bp_w, Cp_w, A_log, right_w, pn_w, pn_b, out_w, axis_w, acc);

    final_kernel<<<(out_size / 4 + 255) / 256, 256>>>(
        (const float4*)x, (const float4*)acc, res_scl, (float4*)out, out_size / 4);
}

// round 4
// speedup vs baseline: 4.1486x; 1.3746x over previous
#include <cuda_runtime.h>
#include <math.h>

// ---------------- scratch (static device globals; no allocation) ----------------
#define NVOX 4194304  // 2*64*32*32*32
static __device__ float g_tmp[NVOX];
static __device__ float g_x1[NVOX];
static __device__ float g_x2[NVOX];
static __device__ float g_xp0[NVOX];
static __device__ float g_xp1[NVOX];
static __device__ float g_xp2[NVOX];
static __device__ float g_o0[NVOX];
static __device__ float g_o1[NVOX];
static __device__ float g_o2[NVOX];

// transposed weights: left 8192 | right 8192 | delta 16384 | out 8192 | bc 4096
#define WT_LEFT  0
#define WT_RIGHT 8192
#define WT_DELTA 16384
#define WT_OUT   32768
#define WT_BC    40960
#define WT_TOTAL 45056
static __device__ float g_wT[WT_TOTAL];

typedef unsigned long long u64t;

// ---------------- f32x2 packed-FMA helpers (Blackwell FFMA2, PTX-only) ----------
__device__ __forceinline__ u64t pk2(float lo, float hi) {
    u64t r; asm("mov.b64 %0, {%1,%2};" : "=l"(r) : "f"(lo), "f"(hi)); return r;
}
__device__ __forceinline__ void upk2(u64t v, float& lo, float& hi) {
    asm("mov.b64 {%0,%1}, %2;" : "=f"(lo), "=f"(hi) : "l"(v));
}
__device__ __forceinline__ u64t fma2(u64t a, u64t b, u64t c) {
    u64t d; asm("fma.rn.f32x2 %0, %1, %2, %3;" : "=l"(d) : "l"(a), "l"(b), "l"(c)); return d;
}

// ---------------- scalar helpers ----------------
__device__ __forceinline__ float softplus_f(float x) {
    return fmaxf(x, 0.f) + log1pf(__expf(-fabsf(x)));
}
__device__ __forceinline__ float silu_f(float x) {
    return x / (1.f + __expf(-x));
}
__device__ __forceinline__ float ex2_fast(float x) {   // MUFU pipe
    float r; asm("ex2.approx.ftz.f32 %0, %1;" : "=f"(r) : "f"(x)); return r;
}

// =================================================================================
// conv3d 3x3x3, C=64->64, +bias. grid (32 h, 8 co-groups of 8, 2 b), block 256.
// =================================================================================
#define CONV_SMEM_BYTES ((13824 + 3468) * 4)
__global__ void __launch_bounds__(256, 3) conv3d_kernel(
    const float* __restrict__ xin, const float* __restrict__ cw,
    const float* __restrict__ cb, float* __restrict__ out)
{
    extern __shared__ float cs[];
    float* WSH = cs;                 // 13824
    float* TIN = cs + 13824;         // 3468
    const u64t* WSH64 = (const u64t*)WSH;

    int tid = threadIdx.x;
    int lane = tid & 31, wid = tid >> 5;
    int h = blockIdx.x;
    int cog = blockIdx.y;            // co base = cog*8
    int b = blockIdx.z;

    for (int idx = tid; idx < 13824; idx += 256) {
        int e = idx & 1, p = (idx >> 1) & 3;
        int kk = (idx >> 3) % 27, ci = (idx >> 3) / 27;
        WSH[idx] = cw[(size_t)(cog * 8 + p * 2 + e) * 1728 + ci * 27 + kk];
    }
    for (int idx = tid; idx < 3468; idx += 256) TIN[idx] = 0.f;

    u64t acc2[16];
#pragma unroll
    for (int i = 0; i < 16; i++) acc2[i] = 0ULL;

    for (int ci = 0; ci < 64; ci++) {
        __syncthreads();
#pragma unroll
        for (int r = 0; r < 3; r++) {
            int j = r * 256 + tid;
            int kh = j >> 8, q = j & 255;
            int w = q >> 3, seg = q & 7;
            int hh = h + kh - 1;
            if (hh >= 0 && hh < 32) {
                const float4 v = *(const float4*)(xin +
                    ((size_t)(b * 64 + ci)) * 32768 + hh * 1024 + w * 32 + seg * 4);
                float* dst = TIN + kh * 1156 + (w + 1) * 34 + 1 + seg * 4;
                dst[0] = v.x; dst[1] = v.y; dst[2] = v.z; dst[3] = v.w;
            }
        }
        __syncthreads();
        const u64t* wb = WSH64 + ci * 108;
#pragma unroll
        for (int kh = 0; kh < 3; kh++) {
            const float* tkh = TIN + kh * 1156;
#pragma unroll
            for (int kw = 0; kw < 3; kw++) {
                u64t wk[3][4];
#pragma unroll
                for (int kd = 0; kd < 3; kd++)
#pragma unroll
                    for (int p = 0; p < 4; p++)
                        wk[kd][p] = wb[(kh * 9 + kw * 3 + kd) * 4 + p];
#pragma unroll
                for (int ws = 0; ws < 4; ws++) {
                    const float* p0 = tkh + (ws * 8 + wid + kw) * 34 + lane;
                    float v0 = p0[0], v1 = p0[1], v2 = p0[2];
                    u64t vv0 = pk2(v0, v0), vv1 = pk2(v1, v1), vv2 = pk2(v2, v2);
#pragma unroll
                    for (int p = 0; p < 4; p++) {
                        acc2[ws * 4 + p] = fma2(vv0, wk[0][p], acc2[ws * 4 + p]);
                        acc2[ws * 4 + p] = fma2(vv1, wk[1][p], acc2[ws * 4 + p]);
                        acc2[ws * 4 + p] = fma2(vv2, wk[2][p], acc2[ws * 4 + p]);
                    }
                }
            }
        }
    }
    float bias[8];
#pragma unroll
    for (int e = 0; e < 8; e++) bias[e] = cb[cog * 8 + e];
#pragma unroll
    for (int ws = 0; ws < 4; ws++) {
        int w = ws * 8 + wid;
        size_t o = ((size_t)(b * 64 + cog * 8)) * 32768 + (size_t)h * 1024 + w * 32 + lane;
#pragma unroll
        for (int p = 0; p < 4; p++) {
            float alo, ahi;
            upk2(acc2[ws * 4 + p], alo, ahi);
            out[o + (size_t)(p * 2) * 32768]     = alo + bias[p * 2];
            out[o + (size_t)(p * 2 + 1) * 32768] = ahi + bias[p * 2 + 1];
        }
    }
}

// ---------------- InstanceNorm3d + LeakyReLU(0.01) + residual (1024 thr) --------
__global__ void inorm_res_kernel(const float* __restrict__ y,
                                 const float* __restrict__ res,
                                 float* __restrict__ out) {
    int bc = blockIdx.x;
    const float4* yp = (const float4*)(y + (size_t)bc * 32768);
    int tid = threadIdx.x;
    int lane = tid & 31, wid = tid >> 5;
    float s1 = 0.f, s2 = 0.f;
    for (int i = tid; i < 8192; i += 1024) {
        float4 v = yp[i];
        s1 += v.x + v.y + v.z + v.w;
        s2 += v.x * v.x + v.y * v.y + v.z * v.z + v.w * v.w;
    }
#pragma unroll
    for (int o = 16; o > 0; o >>= 1) {
        s1 += __shfl_xor_sync(0xffffffffu, s1, o);
        s2 += __shfl_xor_sync(0xffffffffu, s2, o);
    }
    __shared__ float r1[32], r2[32];
    __shared__ float mu_s, rstd_s;
    if (lane == 0) { r1[wid] = s1; r2[wid] = s2; }
    __syncthreads();
    if (tid < 32) {
        float a = r1[tid], c = r2[tid];
#pragma unroll
        for (int o = 16; o > 0; o >>= 1) {
            a += __shfl_xor_sync(0xffffffffu, a, o);
            c += __shfl_xor_sync(0xffffffffu, c, o);
        }
        if (tid == 0) {
            float mu = a * (1.f / 32768.f);
            float var = c * (1.f / 32768.f) - mu * mu;
            mu_s = mu; rstd_s = rsqrtf(var + 1e-5f);
        }
    }
    __syncthreads();
    float mu = mu_s, rstd = rstd_s;
    const float4* rp = (const float4*)(res + (size_t)bc * 32768);
    float4* op = (float4*)(out + (size_t)bc * 32768);
    for (int i = tid; i < 8192; i += 1024) {
        float4 v = yp[i]; float4 r = rp[i]; float4 o; float a;
        a = (v.x - mu) * rstd; o.x = r.x + (a >= 0.f ? a : 0.01f * a);
        a = (v.y - mu) * rstd; o.y = r.y + (a >= 0.f ? a : 0.01f * a);
        a = (v.z - mu) * rstd; o.z = r.z + (a >= 0.f ? a : 0.01f * a);
        a = (v.w - mu) * rstd; o.w = r.w + (a >= 0.f ? a : 0.01f * a);
        op[i] = o;
    }
}

// =================================================================================
// transpose: x2 -> 3 axis-contiguous copies [seq][t][c]; also weight transposes.
// grid 2048 + 176, block 256.
// =================================================================================
__global__ void trans_kernel(const float* __restrict__ x2,
                             const float* __restrict__ left_w, const float* __restrict__ right_w,
                             const float* __restrict__ delta_w, const float* __restrict__ out_w,
                             const float* __restrict__ Bp_w, const float* __restrict__ Cp_w,
                             float* __restrict__ xp0, float* __restrict__ xp1,
                             float* __restrict__ xp2, float* __restrict__ wT)
{
    __shared__ float T[2080];
    int blk = blockIdx.x;
    int tid = threadIdx.x;
    if (blk < 2048) {
        int b = blk >> 10, h = (blk >> 5) & 31, w = blk & 31;
        const float* xb = x2 + (size_t)b * 2097152 + h * 1024 + w * 32;
        for (int e = tid; e < 2048; e += 256) {
            int c = e >> 5, d = e & 31;
            T[d * 65 + c] = xb[(size_t)c * 32768 + d];
        }
        __syncthreads();
        long s2 = (long)blk * 2048;
        long s1 = ((long)(b * 1024 + h * 32)) * 2048 + w * 64;
        long s0 = ((long)(b * 1024 + w * 32)) * 2048 + h * 64;
        for (int e = tid; e < 2048; e += 256) {
            int d = e >> 6, c = e & 63;
            float v = T[d * 65 + c];
            xp2[s2 + e] = v;
            xp1[s1 + (long)d * 2048 + c] = v;
            xp0[s0 + (long)d * 2048 + c] = v;
        }
    } else {
        int i = (blk - 2048) * 256 + tid;
        if (i < 8192)       wT[i] = left_w[(i & 127) * 64 + (i >> 7)];
        else if (i < 16384) { int j = i - 8192;  wT[i] = right_w[(j & 127) * 64 + (j >> 7)]; }
        else if (i < 32768) { int j = i - 16384; wT[i] = delta_w[(j & 127) * 128 + (j >> 7)]; }
        else if (i < 40960) { int j = i - 32768; wT[i] = out_w[(j & 63) * 128 + (j >> 6)]; }
        else if (i < 45056) {
            int j = i - 40960; int k = j >> 5, s = j & 31;
            wT[i] = (s < 16) ? Bp_w[s * 128 + k] : Cp_w[(s - 16) * 128 + k];
        }
    }
}

// =================================================================================
// fused per-sequence Mamba: coalesced gather/scatter, transposed weights,
// stride-36 smem, 128-bit activation broadcasts. grid (2048, 3), 256 thr.
// =================================================================================
#define MB_SMEM_FLOATS 18448
__global__ void __launch_bounds__(256, 3) mamba_kernel(
    const float* __restrict__ xp0, const float* __restrict__ xp1,
    const float* __restrict__ xp2,
    const float* __restrict__ ln_w,  const float* __restrict__ ln_b,
    const float* __restrict__ conv1d_w, const float* __restrict__ conv1d_b,
    const float* __restrict__ delta_b, const float* __restrict__ A_log,
    const float* __restrict__ pn_w,  const float* __restrict__ pn_b,
    const float* __restrict__ wT,
    float* __restrict__ o0, float* __restrict__ o1, float* __restrict__ o2)
{
    extern __shared__ float sm[];
    float* XS   = sm;            // [64][36]
    float* XL   = sm + 2304;     // [128][36] left post conv+silu
    float* DS   = sm + 6912;     // [128][36] raw left -> delta -> YS
    float* GA   = sm + 11520;    // [128][36] raw right -> gate -> out staging
    float* BS   = sm + 16128;    // [16][34]
    float* CS   = sm + 16672;    // [16][34]
    float* MUSD = sm + 17216;    // [64]
    float* A2S  = sm + 17280;    // [16]
    float* LNW  = sm + 17296;    // [64]
    float* LNB  = sm + 17360;    // [64]
    float* CW   = sm + 17424;    // [512]
    float* CB   = sm + 17936;    // [128]
    float* DB   = sm + 18064;    // [128]
    float* PNW  = sm + 18192;    // [128]
    float* PNB  = sm + 18320;    // [128] -> end 18448
    float* YS   = DS;
    float* GA2  = GA;            // [32][64] out staging

    int tid = threadIdx.x;
    int q = blockIdx.x;
    int axis = blockIdx.y;
    const float* xq = ((axis == 0) ? xp0 : (axis == 1) ? xp1 : xp2) + (long)q * 2048;
    float* oa = ((axis == 0) ? o0 : (axis == 1) ? o1 : o2) + (long)q * 2048;

    // ---- phase 0: params + coalesced gather with smem transpose ----
    for (int i = tid; i < 64; i += 256) { LNW[i] = ln_w[i]; LNB[i] = ln_b[i]; }
    for (int i = tid; i < 128; i += 256) {
        CB[i] = conv1d_b[i]; DB[i] = delta_b[i]; PNW[i] = pn_w[i]; PNB[i] = pn_b[i];
    }
    for (int i = tid; i < 512; i += 256) CW[i] = conv1d_w[i];
    if (tid < 16) A2S[tid] = -softplus_f(A_log[tid]) * 1.44269504f;
    for (int e = tid; e < 512; e += 256) {
        float4 v = ((const float4*)xq)[e];
        int t = e >> 4, c0 = (e & 15) * 4;
        XS[c0 * 36 + t] = v.x;       XS[(c0 + 1) * 36 + t] = v.y;
        XS[(c0 + 2) * 36 + t] = v.z; XS[(c0 + 3) * 36 + t] = v.w;
    }
    __syncthreads();

    // ---- phase 1: layernorm over C=64 per timestep ----
    {
        int t = tid >> 3, g = tid & 7;
        float s1 = 0.f, s2 = 0.f;
#pragma unroll
        for (int cc = 0; cc < 8; cc++) {
            float vv = XS[(g * 8 + cc) * 36 + t];
            s1 += vv; s2 += vv * vv;
        }
#pragma unroll
        for (int o = 4; o > 0; o >>= 1) {
            s1 += __shfl_down_sync(0xffffffffu, s1, o);
            s2 += __shfl_down_sync(0xffffffffu, s2, o);
        }
        if (g == 0) {
            float mu = s1 * (1.f / 64.f);
            float var = s2 * (1.f / 64.f) - mu * mu;
            MUSD[t * 2] = mu;
            MUSD[t * 2 + 1] = rsqrtf(var + 1e-5f);
        }
    }
    __syncthreads();
    for (int e = tid; e < 2048; e += 256) {
        int c = e >> 5, t = e & 31;
        XS[c * 36 + t] = (XS[c * 36 + t] - MUSD[t * 2]) * MUSD[t * 2 + 1] * LNW[c] + LNB[c];
    }
    __syncthreads();

    // ---- phase 2: left/right raw projections (transposed weights, ull2 LDS) ----
    {
        int pairidx = tid & 63;
        int half = (tid >> 6) & 1;
        int which = tid >> 7;
        const float* wb = wT + (which ? WT_RIGHT : WT_LEFT);
        u64t accA[8], accB[8];
#pragma unroll
        for (int j = 0; j < 8; j++) { accA[j] = 0ULL; accB[j] = 0ULL; }
#pragma unroll 2
        for (int k = 0; k < 64; k++) {
            float2 w2 = ((const float2*)(wb + k * 128))[pairidx];
            const ulonglong2* xr = (const ulonglong2*)(XS + k * 36) + half * 4;
            u64t waa = pk2(w2.x, w2.x), wbb = pk2(w2.y, w2.y);
#pragma unroll
            for (int j2 = 0; j2 < 4; j2++) {
                ulonglong2 xv = xr[j2];
                accA[2 * j2]     = fma2(xv.x, waa, accA[2 * j2]);
                accA[2 * j2 + 1] = fma2(xv.y, waa, accA[2 * j2 + 1]);
                accB[2 * j2]     = fma2(xv.x, wbb, accB[2 * j2]);
                accB[2 * j2 + 1] = fma2(xv.y, wbb, accB[2 * j2 + 1]);
            }
        }
        float* dstb = which ? GA : DS;
        u64t* dA = (u64t*)(dstb + (2 * pairidx) * 36) + half * 8;
        u64t* dB = (u64t*)(dstb + (2 * pairidx + 1) * 36) + half * 8;
#pragma unroll
        for (int j = 0; j < 8; j++) { dA[j] = accA[j]; dB[j] = accB[j]; }
    }
    __syncthreads();

    // ---- phase 2b: causal conv1d(k=4)+silu on left (DS->XL); silu gate in place ----
    {
        int col = tid >> 1, half = tid & 1;
        int t0 = half * 16;
        float c0w = CW[col * 4], c1w = CW[col * 4 + 1];
        float c2w = CW[col * 4 + 2], c3w = CW[col * 4 + 3];
        float bb = CB[col];
        const float* P = DS + col * 36;
        float* XLr = XL + col * 36;
        float* GAr = GA + col * 36;
#pragma unroll
        for (int dt = 0; dt < 16; dt++) {
            int t = t0 + dt;
            float s = fmaf(c3w, P[t], bb);
            if (t >= 1) s = fmaf(c2w, P[t - 1], s);
            if (t >= 2) s = fmaf(c1w, P[t - 2], s);
            if (t >= 3) s = fmaf(c0w, P[t - 3], s);
            XLr[t] = silu_f(s);
            GAr[t] = silu_f(GAr[t]);
        }
    }
    __syncthreads();

    // ---- phase 3: delta proj (128 thr) + fused B/C proj (128 thr) ----
    if (tid < 128) {
        int pairidx = tid & 63;
        int half = tid >> 6;
        int c0 = 2 * pairidx;
        const float* wd = wT + WT_DELTA;
        u64t accA[8], accB[8];
#pragma unroll
        for (int j = 0; j < 8; j++) { accA[j] = 0ULL; accB[j] = 0ULL; }
#pragma unroll 2
        for (int k = 0; k < 128; k++) {
            float2 w2 = ((const float2*)(wd + k * 128))[pairidx];
            const ulonglong2* xr = (const ulonglong2*)(XL + k * 36) + half * 4;
            u64t waa = pk2(w2.x, w2.x), wbb = pk2(w2.y, w2.y);
#pragma unroll
            for (int j2 = 0; j2 < 4; j2++) {
                ulonglong2 xv = xr[j2];
                accA[2 * j2]     = fma2(xv.x, waa, accA[2 * j2]);
                accA[2 * j2 + 1] = fma2(xv.y, waa, accA[2 * j2 + 1]);
                accB[2 * j2]     = fma2(xv.x, wbb, accB[2 * j2]);
                accB[2 * j2 + 1] = fma2(xv.y, wbb, accB[2 * j2 + 1]);
            }
        }
        float b0 = DB[c0], b1 = DB[c0 + 1];
        float* d0 = DS + c0 * 36 + half * 16;
        float* d1 = DS + (c0 + 1) * 36 + half * 16;
#pragma unroll
        for (int j = 0; j < 8; j++) {
            float a0, a1; upk2(accA[j], a0, a1);
            d0[2 * j]     = fminf(fmaxf(softplus_f(a0 + b0), 1e-4f), 10.f);
            d0[2 * j + 1] = fminf(fmaxf(softplus_f(a1 + b0), 1e-4f), 10.f);
            upk2(accB[j], a0, a1);
            d1[2 * j]     = fminf(fmaxf(softplus_f(a0 + b1), 1e-4f), 10.f);
            d1[2 * j + 1] = fminf(fmaxf(softplus_f(a1 + b1), 1e-4f), 10.f);
        }
    } else {
        int idx = tid & 31;                 // 0-15: B, 16-31: C
        int seg = (tid >> 5) & 3;           // 8 timesteps = 4 u64
        const float* wbc = wT + WT_BC;
        u64t acc[4];
#pragma unroll
        for (int j = 0; j < 4; j++) acc[j] = 0ULL;
#pragma unroll 4
        for (int k = 0; k < 128; k++) {
            float w = wbc[k * 32 + idx];
            const ulonglong2* xr = (const ulonglong2*)(XL + k * 36) + seg * 2;
            ulonglong2 xa = xr[0], xb = xr[1];
            u64t ww = pk2(w, w);
            acc[0] = fma2(xa.x, ww, acc[0]);
            acc[1] = fma2(xa.y, ww, acc[1]);
            acc[2] = fma2(xb.x, ww, acc[2]);
            acc[3] = fma2(xb.y, ww, acc[3]);
        }
        int s = idx & 15;
        float* DST = ((idx < 16) ? BS : CS) + s * 34 + seg * 8;
        u64t* d64 = (u64t*)DST;
#pragma unroll
        for (int j = 0; j < 4; j++) d64[j] = acc[j];
    }
    __syncthreads();

    // ---- phase 4: selective scan (ex2 on MUFU). pair (i, hlf) owns 8 states ----
    {
        int i = tid >> 1;
        int hlf = tid & 1;
        float h[8], a2l[8];
#pragma unroll
        for (int u2 = 0; u2 < 8; u2++) { h[u2] = 0.f; a2l[u2] = A2S[hlf * 8 + u2]; }
        const float* dsrow = DS + i * 36;
        const float* xlrow = XL + i * 36;
        for (int t = 0; t < 32; t++) {
            float d  = dsrow[t];
            float xv = xlrow[t];
            float dx = d * xv;
            float part = 0.f;
#pragma unroll
            for (int u2 = 0; u2 < 8; u2++) {
                int sidx = hlf * 8 + u2;
                float e = ex2_fast(d * a2l[u2]);
                h[u2] = fmaf(e, h[u2], dx * BS[sidx * 34 + t]);
                part = fmaf(h[u2], CS[sidx * 34 + t], part);
            }
            part += __shfl_xor_sync(0xffffffffu, part, 1);
            if (hlf == 0) YS[i * 36 + t] = part;
        }
    }
    __syncthreads();

    // ---- phase 5: gate, then layernorm over di=128 per timestep ----
    for (int e = tid; e < 4096; e += 256) {
        int i = e >> 5, t = e & 31;
        YS[i * 36 + t] *= GA[i * 36 + t];
    }
    __syncthreads();
    {
        int t = tid >> 3, g = tid & 7;
        float s1 = 0.f, s2 = 0.f;
#pragma unroll
        for (int m = 0; m < 16; m++) {
            float vv = YS[(g + m * 8) * 36 + t];
            s1 += vv; s2 += vv * vv;
        }
#pragma unroll
        for (int o = 4; o > 0; o >>= 1) {
            s1 += __shfl_down_sync(0xffffffffu, s1, o);
            s2 += __shfl_down_sync(0xffffffffu, s2, o);
        }
        if (g == 0) {
            float mu = s1 * (1.f / 128.f);
            float var = s2 * (1.f / 128.f) - mu * mu;
            MUSD[t * 2] = mu;
            MUSD[t * 2 + 1] = rsqrtf(var + 1e-5f);
        }
    }
    __syncthreads();
    for (int e = tid; e < 4096; e += 256) {
        int i = e >> 5, t = e & 31;
        YS[i * 36 + t] = (YS[i * 36 + t] - MUSD[t * 2]) * MUSD[t * 2 + 1] * PNW[i] + PNB[i];
    }
    __syncthreads();

    // ---- phase 6: out projection (256 thr) -> [t][c] staging -> coalesced STG ----
    {
        int cp = tid & 31, jq = tid >> 5;
        int c0 = 2 * cp;
        const float* wo = wT + WT_OUT;
        u64t accA[2], accB[2];
        accA[0] = accA[1] = accB[0] = accB[1] = 0ULL;
#pragma unroll 4
        for (int k = 0; k < 128; k++) {
            float2 w2 = ((const float2*)(wo + k * 64))[cp];
            ulonglong2 xv = *((const ulonglong2*)(YS + k * 36) + jq);
            u64t waa = pk2(w2.x, w2.x), wbb = pk2(w2.y, w2.y);
            accA[0] = fma2(xv.x, waa, accA[0]);
            accA[1] = fma2(xv.y, waa, accA[1]);
            accB[0] = fma2(xv.x, wbb, accB[0]);
            accB[1] = fma2(xv.y, wbb, accB[1]);
        }
#pragma unroll
        for (int j = 0; j < 2; j++) {
            int t = jq * 4 + 2 * j;
            float a0, a1; upk2(accA[j], a0, a1);
            GA2[t * 64 + c0]       = a0;
            GA2[(t + 1) * 64 + c0] = a1;
            upk2(accB[j], a0, a1);
            GA2[t * 64 + c0 + 1]       = a0;
            GA2[(t + 1) * 64 + c0 + 1] = a1;
        }
    }
    __syncthreads();
    for (int e = tid; e < 512; e += 256)
        ((float4*)oa)[e] = ((const float4*)GA2)[e];
}

// ---------------- final combine: identity + rs * softmax(axis_w) . outputs -----
__global__ void final_kernel(const float* __restrict__ x,
                             const float* __restrict__ o0, const float* __restrict__ o1,
                             const float* __restrict__ o2,
                             const float* __restrict__ rs, const float* __restrict__ axis_w,
                             float* __restrict__ out)
{
    __shared__ float S[2080];
    int blk = blockIdx.x, tid = threadIdx.x;
    int b = blk >> 10, h = (blk >> 5) & 31, w = blk & 31;
    float a0 = axis_w[0], a1 = axis_w[1], a2 = axis_w[2];
    float m = fmaxf(a0, fmaxf(a1, a2));
    float e0 = __expf(a0 - m), e1 = __expf(a1 - m), e2 = __expf(a2 - m);
    float r = rs[0] / (e0 + e1 + e2);
    float w0 = r * e0, w1 = r * e1, w2 = r * e2;
    long s2 = (long)blk * 2048;
    long s1 = ((long)(b * 1024 + h * 32)) * 2048 + w * 64;
    long s0 = ((long)(b * 1024 + w * 32)) * 2048 + h * 64;
    for (int e = tid; e < 2048; e += 256) {
        int d = e >> 6, c = e & 63;
        S[d * 65 + c] = w0 * o0[s0 + (long)d * 2048 + c]
                      + w1 * o1[s1 + (long)d * 2048 + c]
                      + w2 * o2[s2 + e];
    }
    __syncthreads();
    const float* xb = x + (size_t)b * 2097152 + h * 1024 + w * 32;
    float* ob = out + (size_t)b * 2097152 + h * 1024 + w * 32;
    for (int e = tid; e < 2048; e += 256) {
        int c = e >> 5, d = e & 31;
        ob[(size_t)c * 32768 + d] = xb[(size_t)c * 32768 + d] + S[d * 65 + c];
    }
}

// ---------------- launch ----------------
extern "C" void kernel_launch(void* const* d_in, const int* in_sizes, int n_in,
                              void* d_out, int out_size) {
    (void)in_sizes; (void)n_in; (void)out_size;
    const float* x        = (const float*)d_in[0];
    const float* cr1_w    = (const float*)d_in[1];
    const float* cr1_b    = (const float*)d_in[2];
    const float* cr2_w    = (const float*)d_in[3];
    const float* cr2_b    = (const float*)d_in[4];
    const float* ln_w     = (const float*)d_in[5];
    const float* ln_b     = (const float*)d_in[6];
    const float* left_w   = (const float*)d_in[7];
    const float* conv1d_w = (const float*)d_in[8];
    const float* conv1d_b = (const float*)d_in[9];
    const float* delta_w  = (const float*)d_in[10];
    const float* delta_b  = (const float*)d_in[11];
    const float* Bp_w     = (const float*)d_in[12];
    const float* Cp_w     = (const float*)d_in[13];
    const float* A_log    = (const float*)d_in[14];
    const float* right_w  = (const float*)d_in[15];
    const float* pn_w     = (const float*)d_in[16];
    const float* pn_b     = (const float*)d_in[17];
    const float* out_w    = (const float*)d_in[18];
    const float* res_scl  = (const float*)d_in[19];
    const float* axis_w   = (const float*)d_in[20];
    float* out = (float*)d_out;

    float *tmp, *x1, *x2, *xp0, *xp1, *xp2, *o0, *o1, *o2, *wT;
    cudaGetSymbolAddress((void**)&tmp, g_tmp);
    cudaGetSymbolAddress((void**)&x1, g_x1);
    cudaGetSymbolAddress((void**)&x2, g_x2);
    cudaGetSymbolAddress((void**)&xp0, g_xp0);
    cudaGetSymbolAddress((void**)&xp1, g_xp1);
    cudaGetSymbolAddress((void**)&xp2, g_xp2);
    cudaGetSymbolAddress((void**)&o0, g_o0);
    cudaGetSymbolAddress((void**)&o1, g_o1);
    cudaGetSymbolAddress((void**)&o2, g_o2);
    cudaGetSymbolAddress((void**)&wT, g_wT);

    cudaFuncSetAttribute(conv3d_kernel, cudaFuncAttributeMaxDynamicSharedMemorySize,
                         CONV_SMEM_BYTES);
    cudaFuncSetAttribute(mamba_kernel, cudaFuncAttributeMaxDynamicSharedMemorySize,
                         MB_SMEM_FLOATS * (int)sizeof(float));

    dim3 cg(32, 8, 2);
    conv3d_kernel<<<cg, 256, CONV_SMEM_BYTES>>>(x, cr1_w, cr1_b, tmp);
    inorm_res_kernel<<<128, 1024>>>(tmp, x, x1);
    conv3d_kernel<<<cg, 256, CONV_SMEM_BYTES>>>(x1, cr2_w, cr2_b, tmp);
    inorm_res_kernel<<<128, 1024>>>(tmp, x1, x2);

    trans_kernel<<<2048 + 176, 256>>>(x2, left_w, right_w, delta_w, out_w,
                                      Bp_w, Cp_w, xp0, xp1, xp2, wT);

    mamba_kernel<<<dim3(2048, 3), 256, MB_SMEM_FLOATS * (int)sizeof(float)>>>(
        xp0, xp1, xp2, ln_w, ln_b, conv1d_w, conv1d_b, delta_b, A_log,
        pn_w, pn_b, wT, o0, o1, o2);

    final_kernel<<<2048, 256>>>(x, o0, o1, o2, res_scl, axis_w, out);
}

// round 5
// speedup vs baseline: 4.3153x; 1.0402x over previous
#include <cuda_runtime.h>
#include <math.h>

// ---------------- scratch (static device globals; no allocation) ----------------
#define NVOX 4194304  // 2*64*32*32*32
static __device__ float g_tmp[NVOX];
static __device__ float g_x1[NVOX];
static __device__ float g_x2[NVOX];
static __device__ float g_xp0[NVOX];
static __device__ float g_xp1[NVOX];
static __device__ float g_xp2[NVOX];
static __device__ float g_o0[NVOX];
static __device__ float g_o1[NVOX];
static __device__ float g_o2[NVOX];

// transposed weights: left 8192 | right 8192 | delta 16384 | out 8192 | bc 4096
#define WT_LEFT  0
#define WT_RIGHT 8192
#define WT_DELTA 16384
#define WT_OUT   32768
#define WT_BC    40960
#define WT_TOTAL 45056
static __device__ float g_wT[WT_TOTAL];

typedef unsigned long long u64t;

// ---------------- f32x2 packed-FMA helpers (Blackwell FFMA2, PTX-only) ----------
__device__ __forceinline__ u64t pk2(float lo, float hi) {
    u64t r; asm("mov.b64 %0, {%1,%2};" : "=l"(r) : "f"(lo), "f"(hi)); return r;
}
__device__ __forceinline__ void upk2(u64t v, float& lo, float& hi) {
    asm("mov.b64 {%0,%1}, %2;" : "=f"(lo), "=f"(hi) : "l"(v));
}
__device__ __forceinline__ u64t fma2(u64t a, u64t b, u64t c) {
    u64t d; asm("fma.rn.f32x2 %0, %1, %2, %3;" : "=l"(d) : "l"(a), "l"(b), "l"(c)); return d;
}

// ---------------- scalar helpers ----------------
__device__ __forceinline__ float softplus_f(float x) {
    return fmaxf(x, 0.f) + log1pf(__expf(-fabsf(x)));
}
__device__ __forceinline__ float silu_f(float x) {
    return x / (1.f + __expf(-x));
}
__device__ __forceinline__ float ex2_fast(float x) {   // MUFU pipe
    float r; asm("ex2.approx.ftz.f32 %0, %1;" : "=f"(r) : "f"(x)); return r;
}

// =================================================================================
// conv3d 3x3x3, C=64->64, +bias. grid (32 h, 8 co-groups of 8, 2 b), block 256.
// Double-buffered input tile + per-ci streamed weights; ONE barrier per ci.
// smem: TIN[2][3468] + WS[2][216] = 29.5 KB.
// =================================================================================
#define CONV_SMEM_BYTES ((2 * 3468 + 2 * 216) * 4)
__global__ void __launch_bounds__(256, 3) conv3d_kernel(
    const float* __restrict__ xin, const float* __restrict__ cw,
    const float* __restrict__ cb, float* __restrict__ out)
{
    extern __shared__ float cs[];
    float* TIN = cs;                 // [2][3468]
    float* WS  = cs + 6936;          // [2][216]

    int tid = threadIdx.x;
    int lane = tid & 31, wid = tid >> 5;
    int h = blockIdx.x;
    int cog = blockIdx.y;            // co base = cog*8
    int b = blockIdx.z;

    // zero both tile buffers (halo cells stay zero forever; OOB rows are
    // (h,kh)-dependent only, so they're never written by any ci)
    for (int idx = tid; idx < 6936; idx += 256) TIN[idx] = 0.f;
    __syncthreads();

    // issue loads for ci into buffer buf
    auto load_slice = [&](int ci, int buf) {
        float* T = TIN + buf * 3468;
#pragma unroll
        for (int r = 0; r < 3; r++) {
            int j = r * 256 + tid;              // 0..767 float4
            int kh = j >> 8, qq = j & 255;
            int w = qq >> 3, seg = qq & 7;
            int hh = h + kh - 1;
            if (hh >= 0 && hh < 32) {
                const float4 v = *(const float4*)(xin +
                    ((size_t)(b * 64 + ci)) * 32768 + hh * 1024 + w * 32 + seg * 4);
                float* dst = T + kh * 1156 + (w + 1) * 34 + 1 + seg * 4;
                dst[0] = v.x; dst[1] = v.y; dst[2] = v.z; dst[3] = v.w;
            }
        }
        if (tid < 216) {
            int e = tid & 1, p = (tid >> 1) & 3, kk = tid >> 3;
            WS[buf * 216 + kk * 8 + p * 2 + e] =
                cw[(size_t)(cog * 8 + p * 2 + e) * 1728 + ci * 27 + kk];
        }
    };

    u64t acc2[16];
#pragma unroll
    for (int i = 0; i < 16; i++) acc2[i] = 0ULL;

    load_slice(0, 0);
    __syncthreads();

    for (int ci = 0; ci < 64; ci++) {
        int cur = ci & 1;
        if (ci < 63) load_slice(ci + 1, cur ^ 1);    // overlaps with compute below
        const float* tb = TIN + cur * 3468;
        const u64t* wb = (const u64t*)(WS + cur * 216);
#pragma unroll
        for (int kh = 0; kh < 3; kh++) {
            const float* tkh = tb + kh * 1156;
#pragma unroll
            for (int kw = 0; kw < 3; kw++) {
                u64t wk[3][4];
#pragma unroll
                for (int kd = 0; kd < 3; kd++)
#pragma unroll
                    for (int p = 0; p < 4; p++)
                        wk[kd][p] = wb[(kh * 9 + kw * 3 + kd) * 4 + p];
#pragma unroll
                for (int ws = 0; ws < 4; ws++) {
                    const float* p0 = tkh + (ws * 8 + wid + kw) * 34 + lane;
                    float v0 = p0[0], v1 = p0[1], v2 = p0[2];
                    u64t vv0 = pk2(v0, v0), vv1 = pk2(v1, v1), vv2 = pk2(v2, v2);
#pragma unroll
                    for (int p = 0; p < 4; p++) {
                        acc2[ws * 4 + p] = fma2(vv0, wk[0][p], acc2[ws * 4 + p]);
                        acc2[ws * 4 + p] = fma2(vv1, wk[1][p], acc2[ws * 4 + p]);
                        acc2[ws * 4 + p] = fma2(vv2, wk[2][p], acc2[ws * 4 + p]);
                    }
                }
            }
        }
        __syncthreads();   // loads done + compute done before buffer reuse
    }

    float bias[8];
#pragma unroll
    for (int e = 0; e < 8; e++) bias[e] = cb[cog * 8 + e];
#pragma unroll
    for (int ws = 0; ws < 4; ws++) {
        int w = ws * 8 + wid;
        size_t o = ((size_t)(b * 64 + cog * 8)) * 32768 + (size_t)h * 1024 + w * 32 + lane;
#pragma unroll
        for (int p = 0; p < 4; p++) {
            float alo, ahi;
            upk2(acc2[ws * 4 + p], alo, ahi);
            out[o + (size_t)(p * 2) * 32768]     = alo + bias[p * 2];
            out[o + (size_t)(p * 2 + 1) * 32768] = ahi + bias[p * 2 + 1];
        }
    }
}

// ---------------- InstanceNorm3d + LeakyReLU(0.01) + residual (1024 thr) --------
__global__ void inorm_res_kernel(const float* __restrict__ y,
                                 const float* __restrict__ res,
                                 float* __restrict__ out) {
    int bc = blockIdx.x;
    const float4* yp = (const float4*)(y + (size_t)bc * 32768);
    int tid = threadIdx.x;
    int lane = tid & 31, wid = tid >> 5;
    float s1 = 0.f, s2 = 0.f;
    for (int i = tid; i < 8192; i += 1024) {
        float4 v = yp[i];
        s1 += v.x + v.y + v.z + v.w;
        s2 += v.x * v.x + v.y * v.y + v.z * v.z + v.w * v.w;
    }
#pragma unroll
    for (int o = 16; o > 0; o >>= 1) {
        s1 += __shfl_xor_sync(0xffffffffu, s1, o);
        s2 += __shfl_xor_sync(0xffffffffu, s2, o);
    }
    __shared__ float r1[32], r2[32];
    __shared__ float mu_s, rstd_s;
    if (lane == 0) { r1[wid] = s1; r2[wid] = s2; }
    __syncthreads();
    if (tid < 32) {
        float a = r1[tid], c = r2[tid];
#pragma unroll
        for (int o = 16; o > 0; o >>= 1) {
            a += __shfl_xor_sync(0xffffffffu, a, o);
            c += __shfl_xor_sync(0xffffffffu, c, o);
        }
        if (tid == 0) {
            float mu = a * (1.f / 32768.f);
            float var = c * (1.f / 32768.f) - mu * mu;
            mu_s = mu; rstd_s = rsqrtf(var + 1e-5f);
        }
    }
    __syncthreads();
    float mu = mu_s, rstd = rstd_s;
    const float4* rp = (const float4*)(res + (size_t)bc * 32768);
    float4* op = (float4*)(out + (size_t)bc * 32768);
    for (int i = tid; i < 8192; i += 1024) {
        float4 v = yp[i]; float4 r = rp[i]; float4 o; float a;
        a = (v.x - mu) * rstd; o.x = r.x + (a >= 0.f ? a : 0.01f * a);
        a = (v.y - mu) * rstd; o.y = r.y + (a >= 0.f ? a : 0.01f * a);
        a = (v.z - mu) * rstd; o.z = r.z + (a >= 0.f ? a : 0.01f * a);
        a = (v.w - mu) * rstd; o.w = r.w + (a >= 0.f ? a : 0.01f * a);
        op[i] = o;
    }
}

// =================================================================================
// transpose: x2 -> 3 axis-contiguous copies [seq][t][c]; also weight transposes.
// grid 2048 + 176, block 256.
// =================================================================================
__global__ void trans_kernel(const float* __restrict__ x2,
                             const float* __restrict__ left_w, const float* __restrict__ right_w,
                             const float* __restrict__ delta_w, const float* __restrict__ out_w,
                             const float* __restrict__ Bp_w, const float* __restrict__ Cp_w,
                             float* __restrict__ xp0, float* __restrict__ xp1,
                             float* __restrict__ xp2, float* __restrict__ wT)
{
    __shared__ float T[2080];
    int blk = blockIdx.x;
    int tid = threadIdx.x;
    if (blk < 2048) {
        int b = blk >> 10, h = (blk >> 5) & 31, w = blk & 31;
        const float* xb = x2 + (size_t)b * 2097152 + h * 1024 + w * 32;
        for (int e = tid; e < 2048; e += 256) {
            int c = e >> 5, d = e & 31;
            T[d * 65 + c] = xb[(size_t)c * 32768 + d];
        }
        __syncthreads();
        long s2 = (long)blk * 2048;
        long s1 = ((long)(b * 1024 + h * 32)) * 2048 + w * 64;
        long s0 = ((long)(b * 1024 + w * 32)) * 2048 + h * 64;
        for (int e = tid; e < 2048; e += 256) {
            int d = e >> 6, c = e & 63;
            float v = T[d * 65 + c];
            xp2[s2 + e] = v;
            xp1[s1 + (long)d * 2048 + c] = v;
            xp0[s0 + (long)d * 2048 + c] = v;
        }
    } else {
        int i = (blk - 2048) * 256 + tid;
        if (i < 8192)       wT[i] = left_w[(i & 127) * 64 + (i >> 7)];
        else if (i < 16384) { int j = i - 8192;  wT[i] = right_w[(j & 127) * 64 + (j >> 7)]; }
        else if (i < 32768) { int j = i - 16384; wT[i] = delta_w[(j & 127) * 128 + (j >> 7)]; }
        else if (i < 40960) { int j = i - 32768; wT[i] = out_w[(j & 63) * 128 + (j >> 6)]; }
        else if (i < 45056) {
            int j = i - 40960; int k = j >> 5, s = j & 31;
            wT[i] = (s < 16) ? Bp_w[s * 128 + k] : Cp_w[(s - 16) * 128 + k];
        }
    }
}

// =================================================================================
// fused per-sequence Mamba: coalesced gather/scatter, transposed weights,
// stride-36 smem, 128-bit activation broadcasts, unroll-4 MLP. grid (2048, 3).
// =================================================================================
#define MB_SMEM_FLOATS 18448
__global__ void __launch_bounds__(256, 3) mamba_kernel(
    const float* __restrict__ xp0, const float* __restrict__ xp1,
    const float* __restrict__ xp2,
    const float* __restrict__ ln_w,  const float* __restrict__ ln_b,
    const float* __restrict__ conv1d_w, const float* __restrict__ conv1d_b,
    const float* __restrict__ delta_b, const float* __restrict__ A_log,
    const float* __restrict__ pn_w,  const float* __restrict__ pn_b,
    const float* __restrict__ wT,
    float* __restrict__ o0, float* __restrict__ o1, float* __restrict__ o2)
{
    extern __shared__ float sm[];
    float* XS   = sm;            // [64][36]
    float* XL   = sm + 2304;     // [128][36] left post conv+silu
    float* DS   = sm + 6912;     // [128][36] raw left -> delta -> YS
    float* GA   = sm + 11520;    // [128][36] raw right -> gate -> out staging
    float* BS   = sm + 16128;    // [16][34]
    float* CS   = sm + 16672;    // [16][34]
    float* MUSD = sm + 17216;    // [64]
    float* A2S  = sm + 17280;    // [16]
    float* LNW  = sm + 17296;    // [64]
    float* LNB  = sm + 17360;    // [64]
    float* CW   = sm + 17424;    // [512]
    float* CB   = sm + 17936;    // [128]
    float* DB   = sm + 18064;    // [128]
    float* PNW  = sm + 18192;    // [128]
    float* PNB  = sm + 18320;    // [128] -> end 18448
    float* YS   = DS;
    float* GA2  = GA;            // [32][64] out staging

    int tid = threadIdx.x;
    int q = blockIdx.x;
    int axis = blockIdx.y;
    const float* xq = ((axis == 0) ? xp0 : (axis == 1) ? xp1 : xp2) + (long)q * 2048;
    float* oa = ((axis == 0) ? o0 : (axis == 1) ? o1 : o2) + (long)q * 2048;

    // ---- phase 0: params + coalesced gather with smem transpose ----
    for (int i = tid; i < 64; i += 256) { LNW[i] = ln_w[i]; LNB[i] = ln_b[i]; }
    for (int i = tid; i < 128; i += 256) {
        CB[i] = conv1d_b[i]; DB[i] = delta_b[i]; PNW[i] = pn_w[i]; PNB[i] = pn_b[i];
    }
    for (int i = tid; i < 512; i += 256) CW[i] = conv1d_w[i];
    if (tid < 16) A2S[tid] = -softplus_f(A_log[tid]) * 1.44269504f;
    for (int e = tid; e < 512; e += 256) {
        float4 v = ((const float4*)xq)[e];
        int t = e >> 4, c0 = (e & 15) * 4;
        XS[c0 * 36 + t] = v.x;       XS[(c0 + 1) * 36 + t] = v.y;
        XS[(c0 + 2) * 36 + t] = v.z; XS[(c0 + 3) * 36 + t] = v.w;
    }
    __syncthreads();

    // ---- phase 1: layernorm over C=64 per timestep ----
    {
        int t = tid >> 3, g = tid & 7;
        float s1 = 0.f, s2 = 0.f;
#pragma unroll
        for (int cc = 0; cc < 8; cc++) {
            float vv = XS[(g * 8 + cc) * 36 + t];
            s1 += vv; s2 += vv * vv;
        }
#pragma unroll
        for (int o = 4; o > 0; o >>= 1) {
            s1 += __shfl_down_sync(0xffffffffu, s1, o);
            s2 += __shfl_down_sync(0xffffffffu, s2, o);
        }
        if (g == 0) {
            float mu = s1 * (1.f / 64.f);
            float var = s2 * (1.f / 64.f) - mu * mu;
            MUSD[t * 2] = mu;
            MUSD[t * 2 + 1] = rsqrtf(var + 1e-5f);
        }
    }
    __syncthreads();
    for (int e = tid; e < 2048; e += 256) {
        int c = e >> 5, t = e & 31;
        XS[c * 36 + t] = (XS[c * 36 + t] - MUSD[t * 2]) * MUSD[t * 2 + 1] * LNW[c] + LNB[c];
    }
    __syncthreads();

    // ---- phase 2: left/right raw projections (transposed weights, ull2 LDS) ----
    {
        int pairidx = tid & 63;
        int half = (tid >> 6) & 1;
        int which = tid >> 7;
        const float* wb = wT + (which ? WT_RIGHT : WT_LEFT);
        u64t accA[8], accB[8];
#pragma unroll
        for (int j = 0; j < 8; j++) { accA[j] = 0ULL; accB[j] = 0ULL; }
#pragma unroll 4
        for (int k = 0; k < 64; k++) {
            float2 w2 = ((const float2*)(wb + k * 128))[pairidx];
            const ulonglong2* xr = (const ulonglong2*)(XS + k * 36) + half * 4;
            u64t waa = pk2(w2.x, w2.x), wbb = pk2(w2.y, w2.y);
#pragma unroll
            for (int j2 = 0; j2 < 4; j2++) {
                ulonglong2 xv = xr[j2];
                accA[2 * j2]     = fma2(xv.x, waa, accA[2 * j2]);
                accA[2 * j2 + 1] = fma2(xv.y, waa, accA[2 * j2 + 1]);
                accB[2 * j2]     = fma2(xv.x, wbb, accB[2 * j2]);
                accB[2 * j2 + 1] = fma2(xv.y, wbb, accB[2 * j2 + 1]);
            }
        }
        float* dstb = which ? GA : DS;
        u64t* dA = (u64t*)(dstb + (2 * pairidx) * 36) + half * 8;
        u64t* dB = (u64t*)(dstb + (2 * pairidx + 1) * 36) + half * 8;
#pragma unroll
        for (int j = 0; j < 8; j++) { dA[j] = accA[j]; dB[j] = accB[j]; }
    }
    __syncthreads();

    // ---- phase 2b: causal conv1d(k=4)+silu on left (DS->XL); silu gate in place ----
    {
        int col = tid >> 1, half = tid & 1;
        int t0 = half * 16;
        float c0w = CW[col * 4], c1w = CW[col * 4 + 1];
        float c2w = CW[col * 4 + 2], c3w = CW[col * 4 + 3];
        float bb = CB[col];
        const float* P = DS + col * 36;
        float* XLr = XL + col * 36;
        float* GAr = GA + col * 36;
#pragma unroll
        for (int dt = 0; dt < 16; dt++) {
            int t = t0 + dt;
            float s = fmaf(c3w, P[t], bb);
            if (t >= 1) s = fmaf(c2w, P[t - 1], s);
            if (t >= 2) s = fmaf(c1w, P[t - 2], s);
            if (t >= 3) s = fmaf(c0w, P[t - 3], s);
            XLr[t] = silu_f(s);
            GAr[t] = silu_f(GAr[t]);
        }
    }
    __syncthreads();

    // ---- phase 3: delta proj (128 thr) + fused B/C proj (128 thr) ----
    if (tid < 128) {
        int pairidx = tid & 63;
        int half = tid >> 6;
        int c0 = 2 * pairidx;
        const float* wd = wT + WT_DELTA;
        u64t accA[8], accB[8];
#pragma unroll
        for (int j = 0; j < 8; j++) { accA[j] = 0ULL; accB[j] = 0ULL; }
#pragma unroll 4
        for (int k = 0; k < 128; k++) {
            float2 w2 = ((const float2*)(wd + k * 128))[pairidx];
            const ulonglong2* xr = (const ulonglong2*)(XL + k * 36) + half * 4;
            u64t waa = pk2(w2.x, w2.x), wbb = pk2(w2.y, w2.y);
#pragma unroll
            for (int j2 = 0; j2 < 4; j2++) {
                ulonglong2 xv = xr[j2];
                accA[2 * j2]     = fma2(xv.x, waa, accA[2 * j2]);
                accA[2 * j2 + 1] = fma2(xv.y, waa, accA[2 * j2 + 1]);
                accB[2 * j2]     = fma2(xv.x, wbb, accB[2 * j2]);
                accB[2 * j2 + 1] = fma2(xv.y, wbb, accB[2 * j2 + 1]);
            }
        }
        float b0 = DB[c0], b1 = DB[c0 + 1];
        float* d0 = DS + c0 * 36 + half * 16;
        float* d1 = DS + (c0 + 1) * 36 + half * 16;
#pragma unroll
        for (int j = 0; j < 8; j++) {
            float a0, a1; upk2(accA[j], a0, a1);
            d0[2 * j]     = fminf(fmaxf(softplus_f(a0 + b0), 1e-4f), 10.f);
            d0[2 * j + 1] = fminf(fmaxf(softplus_f(a1 + b0), 1e-4f), 10.f);
            upk2(accB[j], a0, a1);
            d1[2 * j]     = fminf(fmaxf(softplus_f(a0 + b1), 1e-4f), 10.f);
            d1[2 * j + 1] = fminf(fmaxf(softplus_f(a1 + b1), 1e-4f), 10.f);
        }
    } else {
        int idx = tid & 31;                 // 0-15: B, 16-31: C
        int seg = (tid >> 5) & 3;           // 8 timesteps = 4 u64
        const float* wbc = wT + WT_BC;
        u64t acc[4];
#pragma unroll
        for (int j = 0; j < 4; j++) acc[j] = 0ULL;
#pragma unroll 4
        for (int k = 0; k < 128; k++) {
            float w = wbc[k * 32 + idx];
            const ulonglong2* xr = (const ulonglong2*)(XL + k * 36) + seg * 2;
            ulonglong2 xa = xr[0], xb = xr[1];
            u64t ww = pk2(w, w);
            acc[0] = fma2(xa.x, ww, acc[0]);
            acc[1] = fma2(xa.y, ww, acc[1]);
            acc[2] = fma2(xb.x, ww, acc[2]);
            acc[3] = fma2(xb.y, ww, acc[3]);
        }
        int s = idx & 15;
        float* DST = ((idx < 16) ? BS : CS) + s * 34 + seg * 8;
        u64t* d64 = (u64t*)DST;
#pragma unroll
        for (int j = 0; j < 4; j++) d64[j] = acc[j];
    }
    __syncthreads();

    // ---- phase 4: selective scan (ex2 on MUFU). pair (i, hlf) owns 8 states ----
    {
        int i = tid >> 1;
        int hlf = tid & 1;
        float h[8], a2l[8];
#pragma unroll
        for (int u2 = 0; u2 < 8; u2++) { h[u2] = 0.f; a2l[u2] = A2S[hlf * 8 + u2]; }
        const float* dsrow = DS + i * 36;
        const float* xlrow = XL + i * 36;
        for (int t = 0; t < 32; t++) {
            float d  = dsrow[t];
            float xv = xlrow[t];
            float dx = d * xv;
            float part = 0.f;
#pragma unroll
            for (int u2 = 0; u2 < 8; u2++) {
                int sidx = hlf * 8 + u2;
                float e = ex2_fast(d * a2l[u2]);
                h[u2] = fmaf(e, h[u2], dx * BS[sidx * 34 + t]);
                part = fmaf(h[u2], CS[sidx * 34 + t], part);
            }
            part += __shfl_xor_sync(0xffffffffu, part, 1);
            if (hlf == 0) YS[i * 36 + t] = part;
        }
    }
    __syncthreads();

    // ---- phase 5: gate, then layernorm over di=128 per timestep ----
    for (int e = tid; e < 4096; e += 256) {
        int i = e >> 5, t = e & 31;
        YS[i * 36 + t] *= GA[i * 36 + t];
    }
    __syncthreads();
    {
        int t = tid >> 3, g = tid & 7;
        float s1 = 0.f, s2 = 0.f;
#pragma unroll
        for (int m = 0; m < 16; m++) {
            float vv = YS[(g + m * 8) * 36 + t];
            s1 += vv; s2 += vv * vv;
        }
#pragma unroll
        for (int o = 4; o > 0; o >>= 1) {
            s1 += __shfl_down_sync(0xffffffffu, s1, o);
            s2 += __shfl_down_sync(0xffffffffu, s2, o);
        }
        if (g == 0) {
            float mu = s1 * (1.f / 128.f);
            float var = s2 * (1.f / 128.f) - mu * mu;
            MUSD[t * 2] = mu;
            MUSD[t * 2 + 1] = rsqrtf(var + 1e-5f);
        }
    }
    __syncthreads();
    for (int e = tid; e < 4096; e += 256) {
        int i = e >> 5, t = e & 31;
        YS[i * 36 + t] = (YS[i * 36 + t] - MUSD[t * 2]) * MUSD[t * 2 + 1] * PNW[i] + PNB[i];
    }
    __syncthreads();

    // ---- phase 6: out projection (256 thr) -> [t][c] staging -> coalesced STG ----
    {
        int cp = tid & 31, jq = tid >> 5;
        int c0 = 2 * cp;
        const float* wo = wT + WT_OUT;
        u64t accA[2], accB[2];
        accA[0] = accA[1] = accB[0] = accB[1] = 0ULL;
#pragma unroll 4
        for (int k = 0; k < 128; k++) {
            float2 w2 = ((const float2*)(wo + k * 64))[cp];
            ulonglong2 xv = *((const ulonglong2*)(YS + k * 36) + jq);
            u64t waa = pk2(w2.x, w2.x), wbb = pk2(w2.y, w2.y);
            accA[0] = fma2(xv.x, waa, accA[0]);
            accA[1] = fma2(xv.y, waa, accA[1]);
            accB[0] = fma2(xv.x, wbb, accB[0]);
            accB[1] = fma2(xv.y, wbb, accB[1]);
        }
#pragma unroll
        for (int j = 0; j < 2; j++) {
            int t = jq * 4 + 2 * j;
            float a0, a1; upk2(accA[j], a0, a1);
            GA2[t * 64 + c0]       = a0;
            GA2[(t + 1) * 64 + c0] = a1;
            upk2(accB[j], a0, a1);
            GA2[t * 64 + c0 + 1]       = a0;
            GA2[(t + 1) * 64 + c0 + 1] = a1;
        }
    }
    __syncthreads();
    for (int e = tid; e < 512; e += 256)
        ((float4*)oa)[e] = ((const float4*)GA2)[e];
}

// ---------------- final combine: identity + rs * softmax(axis_w) . outputs -----
__global__ void final_kernel(const float* __restrict__ x,
                             const float* __restrict__ o0, const float* __restrict__ o1,
                             const float* __restrict__ o2,
                             const float* __restrict__ rs, const float* __restrict__ axis_w,
                             float* __restrict__ out)
{
    __shared__ float S[2080];
    int blk = blockIdx.x, tid = threadIdx.x;
    int b = blk >> 10, h = (blk >> 5) & 31, w = blk & 31;
    float a0 = axis_w[0], a1 = axis_w[1], a2 = axis_w[2];
    float m = fmaxf(a0, fmaxf(a1, a2));
    float e0 = __expf(a0 - m), e1 = __expf(a1 - m), e2 = __expf(a2 - m);
    float r = rs[0] / (e0 + e1 + e2);
    float w0 = r * e0, w1 = r * e1, w2 = r * e2;
    long s2 = (long)blk * 2048;
    long s1 = ((long)(b * 1024 + h * 32)) * 2048 + w * 64;
    long s0 = ((long)(b * 1024 + w * 32)) * 2048 + h * 64;
    for (int e = tid; e < 2048; e += 256) {
        int d = e >> 6, c = e & 63;
        S[d * 65 + c] = w0 * o0[s0 + (long)d * 2048 + c]
                      + w1 * o1[s1 + (long)d * 2048 + c]
                      + w2 * o2[s2 + e];
    }
    __syncthreads();
    const float* xb = x + (size_t)b * 2097152 + h * 1024 + w * 32;
    float* ob = out + (size_t)b * 2097152 + h * 1024 + w * 32;
    for (int e = tid; e < 2048; e += 256) {
        int c = e >> 5, d = e & 31;
        ob[(size_t)c * 32768 + d] = xb[(size_t)c * 32768 + d] + S[d * 65 + c];
    }
}

// ---------------- launch ----------------
extern "C" void kernel_launch(void* const* d_in, const int* in_sizes, int n_in,
                              void* d_out, int out_size) {
    (void)in_sizes; (void)n_in; (void)out_size;
    const float* x        = (const float*)d_in[0];
    const float* cr1_w    = (const float*)d_in[1];
    const float* cr1_b    = (const float*)d_in[2];
    const float* cr2_w    = (const float*)d_in[3];
    const float* cr2_b    = (const float*)d_in[4];
    const float* ln_w     = (const float*)d_in[5];
    const float* ln_b     = (const float*)d_in[6];
    const float* left_w   = (const float*)d_in[7];
    const float* conv1d_w = (const float*)d_in[8];
    const float* conv1d_b = (const float*)d_in[9];
    const float* delta_w  = (const float*)d_in[10];
    const float* delta_b  = (const float*)d_in[11];
    const float* Bp_w     = (const float*)d_in[12];
    const float* Cp_w     = (const float*)d_in[13];
    const float* A_log    = (const float*)d_in[14];
    const float* right_w  = (const float*)d_in[15];
    const float* pn_w     = (const float*)d_in[16];
    const float* pn_b     = (const float*)d_in[17];
    const float* out_w    = (const float*)d_in[18];
    const float* res_scl  = (const float*)d_in[19];
    const float* axis_w   = (const float*)d_in[20];
    float* out = (float*)d_out;

    float *tmp, *x1, *x2, *xp0, *xp1, *xp2, *o0, *o1, *o2, *wT;
    cudaGetSymbolAddress((void**)&tmp, g_tmp);
    cudaGetSymbolAddress((void**)&x1, g_x1);
    cudaGetSymbolAddress((void**)&x2, g_x2);
    cudaGetSymbolAddress((void**)&xp0, g_xp0);
    cudaGetSymbolAddress((void**)&xp1, g_xp1);
    cudaGetSymbolAddress((void**)&xp2, g_xp2);
    cudaGetSymbolAddress((void**)&o0, g_o0);
    cudaGetSymbolAddress((void**)&o1, g_o1);
    cudaGetSymbolAddress((void**)&o2, g_o2);
    cudaGetSymbolAddress((void**)&wT, g_wT);

    cudaFuncSetAttribute(conv3d_kernel, cudaFuncAttributeMaxDynamicSharedMemorySize,
                         CONV_SMEM_BYTES);
    cudaFuncSetAttribute(mamba_kernel, cudaFuncAttributeMaxDynamicSharedMemorySize,
                         MB_SMEM_FLOATS * (int)sizeof(float));

    dim3 cg(32, 8, 2);
    conv3d_kernel<<<cg, 256, CONV_SMEM_BYTES>>>(x, cr1_w, cr1_b, tmp);
    inorm_res_kernel<<<128, 1024>>>(tmp, x, x1);
    conv3d_kernel<<<cg, 256, CONV_SMEM_BYTES>>>(x1, cr2_w, cr2_b, tmp);
    inorm_res_kernel<<<128, 1024>>>(tmp, x1, x2);

    trans_kernel<<<2048 + 176, 256>>>(x2, left_w, right_w, delta_w, out_w,
                                      Bp_w, Cp_w, xp0, xp1, xp2, wT);

    mamba_kernel<<<dim3(2048, 3), 256, MB_SMEM_FLOATS * (int)sizeof(float)>>>(
        xp0, xp1, xp2, ln_w, ln_b, conv1d_w, conv1d_b, delta_b, A_log,
        pn_w, pn_b, wT, o0, o1, o2);

    final_kernel<<<2048, 256>>>(x, o0, o1, o2, res_scl, axis_w, out);
}